// round 5
// baseline (speedup 1.0000x reference)
#include <cuda_runtime.h>
#include <cuda_fp16.h>
#include <cstdint>

#if defined(__CUDA_ARCH_FEAT_SM103_ALL) || defined(__CUDA_ARCH_FEAT_SM100_ALL)
#define HX_HAS_TCGEN05 1
#else
#define HX_HAS_TCGEN05 0
#endif

#define D        128
#define NQ       4096
#define NKEYS    65536
#define NSPLIT   4
#define KEYS_PER_SPLIT (NKEYS / NSPLIT)
#define BN       64
#define NT       (KEYS_PER_SPLIT / BN)    // 256
#define NCTA     128
#define NTHREADS 416

__device__ __half g_qhi[NQ * D];
__device__ __half g_qlo[NQ * D];
__device__ __half g_khi[(size_t)NKEYS * D];
__device__ __half g_klo[(size_t)NKEYS * D];
__device__ __half g_kthi[(size_t)D * NKEYS];   // [d][n]
__device__ __half g_vthi[(size_t)D * NKEYS];   // [d][n]
__device__ float  g_ok[(size_t)NSPLIT * NQ * D];
__device__ float  g_ov[(size_t)NSPLIT * NQ * D];
__device__ float  g_m[NSPLIT * NQ];
__device__ float  g_l[NSPLIT * NQ];

__device__ __forceinline__ uint32_t hx_smem_u32(const void* p) {
    uint32_t a;
    asm("{ .reg .u64 t; cvta.to.shared.u64 t, %1; cvt.u32.u64 %0, t; }" : "=r"(a) : "l"(p));
    return a;
}
__device__ __forceinline__ uint32_t hx_elect() {
    uint32_t p;
    asm volatile("{\n\t.reg .pred p;\n\telect.sync _|p, 0xFFFFFFFF;\n\t"
                 "selp.b32 %0, 1, 0, p;\n\t}" : "=r"(p));
    return p;
}
#define HX_TCALLOC(sa, n) \
    asm volatile("tcgen05.alloc.cta_group::1.sync.aligned.shared::cta.b32 [%0], %1;" \
                 :: "r"((uint32_t)(sa)), "r"((uint32_t)(n)) : "memory")
#define HX_TCDEALLOC(t, n) \
    asm volatile("tcgen05.dealloc.cta_group::1.sync.aligned.b32 %0, %1;" :: "r"(t), "r"(n))
#define HX_COMMIT(mb) \
    asm volatile("tcgen05.commit.cta_group::1.mbarrier::arrive::one.shared::cluster.b64 [%0];" \
                 :: "r"((uint32_t)(mb)) : "memory")
#define HX_FENCE_BEFORE() asm volatile("tcgen05.fence::before_thread_sync;" ::: "memory")
#define HX_FENCE_AFTER()  asm volatile("tcgen05.fence::after_thread_sync;" ::: "memory")
#define HX_WAIT_LD()      asm volatile("tcgen05.wait::ld.sync.aligned;" ::: "memory")
#define HX_FENCE_ASYNC()  asm volatile("fence.proxy.async.shared::cta;" ::: "memory")
#define HX_MBINIT(mb, c) \
    asm volatile("mbarrier.init.shared.b64 [%0], %1;" :: "r"((uint32_t)(mb)), "r"((uint32_t)(c)) : "memory")
#define HX_MBARRIVE(mb) \
    asm volatile("mbarrier.arrive.shared.b64 _, [%0];" :: "r"((uint32_t)(mb)) : "memory")

#define HX_MBWAIT(mbaddr, ph) do {                                            \
    uint32_t _mb = (uint32_t)(mbaddr);                                        \
    uint32_t _pa = (uint32_t)(ph);                                            \
    uint32_t _done;                                                           \
    asm volatile("{\n\t.reg .pred p;\n\t"                                     \
        "mbarrier.try_wait.parity.acquire.cta.shared::cta.b64 p, [%1], %2;\n\t" \
        "selp.b32 %0, 1, 0, p;\n\t}" : "=r"(_done) : "r"(_mb), "r"(_pa) : "memory"); \
    if (!_done) {                                                             \
        asm volatile("{\n\t.reg .pred P1;\n\t"                                \
            "WL_%=:\n\t"                                                      \
            "mbarrier.try_wait.parity.acquire.cta.shared::cta.b64 P1, [%0], %1, 0x989680;\n\t" \
            "@P1 bra.uni WD_%=;\n\t"                                          \
            "bra.uni WL_%=;\n\t"                                              \
            "WD_%=:\n\t}" :: "r"(_mb), "r"(_pa) : "memory");                  \
    }                                                                         \
} while (0)

#define HX_LDTM_X32(r, addr) \
    asm volatile("tcgen05.ld.sync.aligned.32x32b.x32.b32 "                    \
        "{%0, %1, %2, %3, %4, %5, %6, %7, %8, %9, %10, %11, %12, %13, %14, %15, " \
        " %16, %17, %18, %19, %20, %21, %22, %23, %24, %25, %26, %27, %28, %29, %30, %31}, [%32];" \
        : "=r"((r)[0]),  "=r"((r)[1]),  "=r"((r)[2]),  "=r"((r)[3]),          \
          "=r"((r)[4]),  "=r"((r)[5]),  "=r"((r)[6]),  "=r"((r)[7]),          \
          "=r"((r)[8]),  "=r"((r)[9]),  "=r"((r)[10]), "=r"((r)[11]),         \
          "=r"((r)[12]), "=r"((r)[13]), "=r"((r)[14]), "=r"((r)[15]),         \
          "=r"((r)[16]), "=r"((r)[17]), "=r"((r)[18]), "=r"((r)[19]),         \
          "=r"((r)[20]), "=r"((r)[21]), "=r"((r)[22]), "=r"((r)[23]),         \
          "=r"((r)[24]), "=r"((r)[25]), "=r"((r)[26]), "=r"((r)[27]),         \
          "=r"((r)[28]), "=r"((r)[29]), "=r"((r)[30]), "=r"((r)[31])          \
        : "r"(addr))

__device__ __forceinline__ void hx_mma_f16_ss(uint32_t d, uint64_t a, uint64_t b,
                                              uint32_t idesc, uint32_t acc) {
#if HX_HAS_TCGEN05
    asm volatile("{\n\t.reg .pred p;\n\tsetp.ne.u32 p, %5, 0;\n\t"
        "tcgen05.mma.cta_group::1.kind::f16 [%0], %1, %2, %3, {%4, %4, %4, %4}, p;\n\t}"
        :: "r"(d), "l"(a), "l"(b), "r"(idesc), "r"(0u), "r"(acc) : "memory");
#endif
}

// K-major SW128 desc (LBO=1, SBO=64)
__device__ __forceinline__ uint64_t hx_desc_k(uint32_t sa) {
    return ((uint64_t)2 << 61) | ((uint64_t)1 << 46) | ((uint64_t)64 << 32) |
           ((uint64_t)1 << 16) | ((uint64_t)(sa >> 4) & 0x3FFF);
}

// idesc f16/f32: QK N=64; PV N=128 (both K-major A and B)
#define HX_IDESC_QK 0x08100010u
#define HX_IDESC_PV 0x08200010u

// swizzled offsets: Q 128rx256B (2 atom cols x16), K 64rx256B (2x8), 128rx128B (1x16)
__device__ __forceinline__ uint32_t hx_offQ(int r, int c8) {
    uint32_t off = (uint32_t)((r >> 3) + ((c8 >> 3) << 4)) * 1024u +
                   (uint32_t)(r & 7) * 128u + (uint32_t)((c8 & 7) << 4);
    return off ^ ((off >> 3) & 0x70u);
}
__device__ __forceinline__ uint32_t hx_off64w(int r, int c8) {
    uint32_t off = (uint32_t)((r >> 3) + ((c8 >> 3) << 3)) * 1024u +
                   (uint32_t)(r & 7) * 128u + (uint32_t)((c8 & 7) << 4);
    return off ^ ((off >> 3) & 0x70u);
}
__device__ __forceinline__ uint32_t hx_off128n(int r, int c8) {
    uint32_t off = (uint32_t)(r >> 3) * 1024u + (uint32_t)(r & 7) * 128u + (uint32_t)(c8 << 4);
    return off ^ ((off >> 3) & 0x70u);
}
__device__ __forceinline__ uint64_t hx_koffQ(int k) {
    return (k < 4) ? (uint64_t)(k * 2) : (uint64_t)(1024 + (k - 4) * 2);
}
__device__ __forceinline__ uint64_t hx_koffK(int k) {
    return (k < 4) ? (uint64_t)(k * 2) : (uint64_t)(512 + (k - 4) * 2);
}

#define MB_KF(s) (8 + 8 * (s))
#define MB_QD(s) (24 + 8 * (s))
#define MB_SR(s) (40 + 8 * (s))
#define MB_PF(s) (56 + 8 * (s))
#define MB_PD(s) (72 + 8 * (s))
#define OFF_PART 128
#define OFF_RED  1280
#define OFF_QHI  2048
#define OFF_QLO  (OFF_QHI + 32768)
#define OFF_ST0  (OFF_QLO + 32768)        // 67584, 1024-aligned
#define STB      81920
#define ST_KHI(s) (OFF_ST0 + (s) * STB)
#define ST_KLO(s) (ST_KHI(s) + 16384)
#define ST_KT(s)  (ST_KHI(s) + 32768)
#define ST_VT(s)  (ST_KHI(s) + 49152)
#define ST_P(s)   (ST_KHI(s) + 65536)
#define SMEM_TOTAL (OFF_ST0 + 2 * STB)    // 231424 <= 232448

#define TM_S(s) ((s) * 64)
#define TM_OK   128
#define TM_OV   256

__global__ void prep_hilo(const float* __restrict__ q, const float* __restrict__ k) {
    int i = blockIdx.x * blockDim.x + threadIdx.x;
    if (i < NKEYS * D) {
        float x = k[i];
        __half h = __float2half_rn(x);
        g_khi[i] = h;
        g_klo[i] = __float2half_rn(x - __half2float(h));
    }
    if (i < NQ * D) {
        float x = q[i];
        __half h = __float2half_rn(x);
        g_qhi[i] = h;
        g_qlo[i] = __float2half_rn(x - __half2float(h));
    }
}

__global__ void prep_transpose(const float* __restrict__ k, const float* __restrict__ v) {
    __shared__ __half sm[32][33];
    const float* src = blockIdx.z ? v : k;
    __half* dst = blockIdx.z ? g_vthi : g_kthi;
    int n0 = blockIdx.x * 32;
    int d0 = blockIdx.y * 32;
    #pragma unroll
    for (int yy = threadIdx.y; yy < 32; yy += 8)
        sm[yy][threadIdx.x] = __float2half_rn(src[(size_t)(n0 + yy) * D + d0 + threadIdx.x]);
    __syncthreads();
    #pragma unroll
    for (int yy = threadIdx.y; yy < 32; yy += 8)
        dst[(size_t)(d0 + yy) * NKEYS + n0 + threadIdx.x] = sm[threadIdx.x][yy];
}

__global__ __launch_bounds__(NTHREADS, 1) void flash_main() {
#if HX_HAS_TCGEN05
    extern __shared__ char smem[];
    uint32_t sb = hx_smem_u32(smem);
    int tid = threadIdx.x;
    int wid = tid >> 5;
    int lane = tid & 31;

    int split = blockIdx.x & (NSPLIT - 1);
    int q0 = (blockIdx.x >> 2) * 128;
    int n0 = split * KEYS_PER_SPLIT;

    if (wid == 12) HX_TCALLOC(sb, 512);
    if (tid == 0) {
        HX_MBINIT(sb + MB_KF(0), 128); HX_MBINIT(sb + MB_KF(1), 128);
        HX_MBINIT(sb + MB_QD(0), 1);   HX_MBINIT(sb + MB_QD(1), 1);
        HX_MBINIT(sb + MB_SR(0), 256); HX_MBINIT(sb + MB_SR(1), 256);
        HX_MBINIT(sb + MB_PF(0), 256); HX_MBINIT(sb + MB_PF(1), 256);
        HX_MBINIT(sb + MB_PD(0), 1);   HX_MBINIT(sb + MB_PD(1), 1);
    }
    __syncthreads();
    uint32_t tmem;
    asm volatile("ld.shared.b32 %0, [%1];" : "=r"(tmem) : "r"(sb));

    if (tid < 256) {
        #pragma unroll
        for (int i = 0; i < 8; ++i) {
            int idx = tid + i * 256;
            int r = idx >> 4, c8 = idx & 15;
            size_t go = (size_t)(q0 + r) * D + (size_t)c8 * 8;
            *(uint4*)(smem + OFF_QHI + hx_offQ(r, c8)) = *(const uint4*)(g_qhi + go);
            *(uint4*)(smem + OFF_QLO + hx_offQ(r, c8)) = *(const uint4*)(g_qlo + go);
        }
        HX_FENCE_ASYNC();
    }
    __syncthreads();

    const bool is_load = (tid >= 256 && tid < 384);
    const bool is_mma  = (tid >= 384);
    int lq[2] = {0,0}, lp[2] = {0,0};
    int kf[2] = {0,0}, sr[2] = {0,0}, pf[2] = {0,0};
    int cq[2] = {0,0}, cp[2] = {0,0};
    float m = -1e30f, lsum = 0.0f;
    int colh = wid >> 2;
    int row  = 32 * (wid & 3) + lane;

    uint32_t is_e = 0;
    uint64_t dqh = 0, dql = 0, dkh[2], dkl[2], dpd[2], dkt[2], dvt[2];
    if (is_mma) {
        is_e = hx_elect();
        dqh = hx_desc_k(sb + OFF_QHI);
        dql = hx_desc_k(sb + OFF_QLO);
        #pragma unroll
        for (int s = 0; s < 2; ++s) {
            dkh[s] = hx_desc_k(sb + ST_KHI(s));
            dkl[s] = hx_desc_k(sb + ST_KLO(s));
            dkt[s] = hx_desc_k(sb + ST_KT(s));
            dvt[s] = hx_desc_k(sb + ST_VT(s));
            dpd[s] = hx_desc_k(sb + ST_P(s));
        }
    }

    // ===================== PASS A: row max ==================================
    if (is_load) {
        int lt = tid - 256;
        for (int t = 0; t < NT; ++t) {
            int s = t & 1;
            if (t >= 2) { HX_MBWAIT(sb + MB_QD(s), lq[s]); lq[s] ^= 1; }
            const __half* src = g_khi + (size_t)(n0 + t * BN) * D;
            #pragma unroll
            for (int j = 0; j < 8; ++j) {
                int idx = lt + j * 128;
                int r = idx >> 4, c8 = idx & 15;
                *(uint4*)(smem + ST_KHI(s) + hx_off64w(r, c8)) =
                    *(const uint4*)(src + (size_t)r * D + (size_t)c8 * 8);
            }
            HX_FENCE_ASYNC();
            HX_MBARRIVE(sb + MB_KF(s));
        }
    } else if (is_mma) {
        for (int t = 0; t < NT; ++t) {
            int s = t & 1;
            HX_MBWAIT(sb + MB_KF(s), kf[s]); kf[s] ^= 1;
            if (t >= 2) { HX_MBWAIT(sb + MB_SR(s), sr[s]); sr[s] ^= 1; }
            HX_FENCE_AFTER();
            if (is_e) {
                #pragma unroll
                for (int kk = 0; kk < 8; ++kk)
                    hx_mma_f16_ss(tmem + TM_S(s), dqh + hx_koffQ(kk),
                                  dkh[s] + hx_koffK(kk), HX_IDESC_QK, kk > 0);
                HX_COMMIT(sb + MB_QD(s));
            }
        }
    } else {
        for (int t = 0; t < NT; ++t) {
            int s = t & 1;
            HX_MBWAIT(sb + MB_QD(s), cq[s]); cq[s] ^= 1;
            HX_FENCE_AFTER();
            uint32_t r[32];
            HX_LDTM_X32(r, tmem + TM_S(s) + 32 * colh);
            HX_WAIT_LD();
            HX_FENCE_BEFORE();
            HX_MBARRIVE(sb + MB_SR(s));
            #pragma unroll
            for (int j = 0; j < 32; ++j)
                m = fmaxf(m, __uint_as_float(r[j]));
        }
        float* part = (float*)(smem + OFF_PART);
        float* red  = (float*)(smem + OFF_RED);
        part[tid] = m;
        asm volatile("bar.sync 1, 256;" ::: "memory");
        if (tid < 128) red[tid] = fmaxf(part[tid], part[tid + 128]);
        asm volatile("bar.sync 1, 256;" ::: "memory");
        m = red[row];
        asm volatile("bar.sync 1, 256;" ::: "memory");
    }
    __syncthreads();

    // ===================== PASS B: softmax + PV =============================
    if (is_load) {
        int lt = tid - 256;
        for (int t = 0; t < NT; ++t) {
            int s = t & 1;
            if (t < 2) { HX_MBWAIT(sb + MB_QD(s), lq[s]); lq[s] ^= 1; }
            else       { HX_MBWAIT(sb + MB_PD(s), lp[s]); lp[s] ^= 1; }
            size_t nb = (size_t)(n0 + t * BN);
            const __half* skh = g_khi + nb * D;
            const __half* skl = g_klo + nb * D;
            #pragma unroll
            for (int j = 0; j < 8; ++j) {
                int idx = lt + j * 128;
                int r = idx >> 4, c8 = idx & 15;
                uint32_t so = hx_off64w(r, c8);
                size_t go = (size_t)r * D + (size_t)c8 * 8;
                *(uint4*)(smem + ST_KHI(s) + so) = *(const uint4*)(skh + go);
                *(uint4*)(smem + ST_KLO(s) + so) = *(const uint4*)(skl + go);
            }
            const __half* skt = g_kthi + nb;
            const __half* svt = g_vthi + nb;
            #pragma unroll
            for (int j = 0; j < 8; ++j) {
                int idx = lt + j * 128;
                int r = idx >> 3, c8 = idx & 7;
                uint32_t so = hx_off128n(r, c8);
                size_t go = (size_t)r * NKEYS + (size_t)c8 * 8;
                *(uint4*)(smem + ST_KT(s) + so) = *(const uint4*)(skt + go);
                *(uint4*)(smem + ST_VT(s) + so) = *(const uint4*)(svt + go);
            }
            HX_FENCE_ASYNC();
            HX_MBARRIVE(sb + MB_KF(s));
        }
    } else if (is_mma) {
        for (int t = 0; t < NT; ++t) {
            int s = t & 1;
            HX_MBWAIT(sb + MB_KF(s), kf[s]); kf[s] ^= 1;
            HX_MBWAIT(sb + MB_SR(s), sr[s]); sr[s] ^= 1;
            HX_FENCE_AFTER();
            if (is_e) {
                #pragma unroll
                for (int kk = 0; kk < 8; ++kk)
                    hx_mma_f16_ss(tmem + TM_S(s), dqh + hx_koffQ(kk),
                                  dkh[s] + hx_koffK(kk), HX_IDESC_QK, kk > 0);
                #pragma unroll
                for (int kk = 0; kk < 8; ++kk)
                    hx_mma_f16_ss(tmem + TM_S(s), dqh + hx_koffQ(kk),
                                  dkl[s] + hx_koffK(kk), HX_IDESC_QK, 1u);
                #pragma unroll
                for (int kk = 0; kk < 8; ++kk)
                    hx_mma_f16_ss(tmem + TM_S(s), dql + hx_koffQ(kk),
                                  dkh[s] + hx_koffK(kk), HX_IDESC_QK, 1u);
                HX_COMMIT(sb + MB_QD(s));
            }
            if (t >= 1) {
                int tp = t - 1, sp = tp & 1;
                HX_MBWAIT(sb + MB_PF(sp), pf[sp]); pf[sp] ^= 1;
                HX_FENCE_AFTER();
                if (is_e) {
                    #pragma unroll
                    for (int kk = 0; kk < 4; ++kk) {
                        uint32_t acc = (tp > 0 || kk > 0) ? 1u : 0u;
                        hx_mma_f16_ss(tmem + TM_OK, dpd[sp] + 2 * kk,
                                      dkt[sp] + 2 * kk, HX_IDESC_PV, acc);
                        hx_mma_f16_ss(tmem + TM_OV, dpd[sp] + 2 * kk,
                                      dvt[sp] + 2 * kk, HX_IDESC_PV, acc);
                    }
                    HX_COMMIT(sb + MB_PD(sp));
                }
            }
        }
        {
            int sp = (NT - 1) & 1;
            HX_MBWAIT(sb + MB_PF(sp), pf[sp]); pf[sp] ^= 1;
            HX_FENCE_AFTER();
            if (is_e) {
                #pragma unroll
                for (int kk = 0; kk < 4; ++kk) {
                    hx_mma_f16_ss(tmem + TM_OK, dpd[sp] + 2 * kk,
                                  dkt[sp] + 2 * kk, HX_IDESC_PV, 1u);
                    hx_mma_f16_ss(tmem + TM_OV, dpd[sp] + 2 * kk,
                                  dvt[sp] + 2 * kk, HX_IDESC_PV, 1u);
                }
                HX_COMMIT(sb + MB_PD(sp));
            }
        }
    } else {
        for (int t = 0; t < NT; ++t) {
            int s = t & 1;
            HX_MBWAIT(sb + MB_QD(s), cq[s]); cq[s] ^= 1;
            HX_FENCE_AFTER();
            uint32_t r[32];
            HX_LDTM_X32(r, tmem + TM_S(s) + 32 * colh);
            HX_WAIT_LD();
            HX_FENCE_BEFORE();
            HX_MBARRIVE(sb + MB_SR(s));
            if (t >= 2) { HX_MBWAIT(sb + MB_PD(s), cp[s]); cp[s] ^= 1; }
            #pragma unroll
            for (int u = 0; u < 4; ++u) {
                uint32_t h2[4];
                #pragma unroll
                for (int j = 0; j < 4; ++j) {
                    float p0 = __expf(__uint_as_float(r[8 * u + 2 * j])     - m);
                    float p1 = __expf(__uint_as_float(r[8 * u + 2 * j + 1]) - m);
                    lsum += p0 + p1;
                    __half2 hh = __floats2half2_rn(p0, p1);
                    h2[j] = *(uint32_t*)&hh;
                }
                *(uint4*)(smem + ST_P(s) + hx_off128n(row, 4 * colh + u)) =
                    make_uint4(h2[0], h2[1], h2[2], h2[3]);
            }
            HX_FENCE_ASYNC();
            HX_MBARRIVE(sb + MB_PF(s));
        }
        HX_MBWAIT(sb + MB_PD(0), cp[0]);
        HX_MBWAIT(sb + MB_PD(1), cp[1]);
        HX_FENCE_AFTER();

        float* part = (float*)(smem + OFF_PART);
        float* red  = (float*)(smem + OFF_RED);
        part[tid] = lsum;
        asm volatile("bar.sync 1, 256;" ::: "memory");
        if (tid < 128) {
            red[tid] = part[tid] + part[tid + 128];
            g_m[split * NQ + q0 + tid] = m;
            g_l[split * NQ + q0 + tid] = red[tid];
        }

        size_t base = ((size_t)split * NQ + q0 + row) * D + 64 * colh;
        #pragma unroll
        for (int c = 0; c < 2; ++c) {
            uint32_t rk[32];
            HX_LDTM_X32(rk, tmem + TM_OK + 64 * colh + 32 * c);
            HX_WAIT_LD();
            #pragma unroll
            for (int j = 0; j < 32; ++j)
                g_ok[base + 32 * c + j] = __uint_as_float(rk[j]);
        }
        #pragma unroll
        for (int c = 0; c < 2; ++c) {
            uint32_t rv[32];
            HX_LDTM_X32(rv, tmem + TM_OV + 64 * colh + 32 * c);
            HX_WAIT_LD();
            #pragma unroll
            for (int j = 0; j < 32; ++j)
                g_ov[base + 32 * c + j] = __uint_as_float(rv[j]);
        }
        HX_FENCE_BEFORE();
    }
    __syncthreads();
    if (wid == 12) HX_TCDEALLOC(tmem, 512);
#endif
}

__global__ void reduce_kernel(float* __restrict__ out) {
    int q = blockIdx.x;
    int d = threadIdx.x;
    float m0 = g_m[q], m1 = g_m[NQ + q], m2 = g_m[2 * NQ + q], m3 = g_m[3 * NQ + q];
    float ms = fmaxf(fmaxf(m0, m1), fmaxf(m2, m3));
    float w0 = __expf(m0 - ms), w1 = __expf(m1 - ms);
    float w2 = __expf(m2 - ms), w3 = __expf(m3 - ms);
    float inv = 1.0f / (g_l[q] * w0 + g_l[NQ + q] * w1 +
                        g_l[2 * NQ + q] * w2 + g_l[3 * NQ + q] * w3);
    size_t i0 = (size_t)q * D + d;
    size_t i1 = ((size_t)NQ + q) * D + d;
    size_t i2 = ((size_t)2 * NQ + q) * D + d;
    size_t i3 = ((size_t)3 * NQ + q) * D + d;
    float ok = g_ok[i0] * w0 + g_ok[i1] * w1 + g_ok[i2] * w2 + g_ok[i3] * w3;
    float ov = g_ov[i0] * w0 + g_ov[i1] * w1 + g_ov[i2] * w2 + g_ov[i3] * w3;
    out[(size_t)q * D + d] = ok * inv;
    out[(size_t)NQ * D + (size_t)q * D + d] = ov * inv;
}

extern "C" void kernel_launch(void* const* d_in, const int* in_sizes, int n_in,
                              void* d_out, int out_size) {
    const float* q = (const float*)d_in[0];
    const float* k = (const float*)d_in[1];
    const float* v = (const float*)d_in[2];
    float* out = (float*)d_out;
    (void)in_sizes; (void)n_in; (void)out_size;

    cudaFuncSetAttribute(flash_main, cudaFuncAttributeMaxDynamicSharedMemorySize, SMEM_TOTAL);
    prep_hilo<<<(NKEYS * D) / 256, 256>>>(q, k);
    dim3 gt(NKEYS / 32, D / 32, 2), bt(32, 8);
    prep_transpose<<<gt, bt>>>(k, v);
    flash_main<<<NCTA, NTHREADS, SMEM_TOTAL>>>();
    reduce_kernel<<<NQ, 128>>>(out);
}

// round 6
// speedup vs baseline: 2.2025x; 2.2025x over previous
#include <cuda_runtime.h>
#include <cuda_fp16.h>
#include <cstdint>

#if defined(__CUDA_ARCH_FEAT_SM103_ALL) || defined(__CUDA_ARCH_FEAT_SM100_ALL)
#define HX_HAS_TCGEN05 1
#else
#define HX_HAS_TCGEN05 0
#endif

#define D        128
#define NQ       4096
#define NKEYS    65536
#define NSPLIT   4
#define KEYS_PER_SPLIT (NKEYS / NSPLIT)
#define BNA      128
#define NTA      (KEYS_PER_SPLIT / BNA)   // 128
#define BNB      64
#define NTB      (KEYS_PER_SPLIT / BNB)   // 256
#define NCTA     128
#define NTHREADS 256

__device__ __half g_qhi[NQ * D];
__device__ __half g_qlo[NQ * D];
__device__ __half g_khi[(size_t)NKEYS * D];
__device__ __half g_klo[(size_t)NKEYS * D];
__device__ __half g_kthi[(size_t)D * NKEYS];   // [d][n]
__device__ __half g_vthi[(size_t)D * NKEYS];   // [d][n]
__device__ float  g_ok[(size_t)NSPLIT * NQ * D];
__device__ float  g_ov[(size_t)NSPLIT * NQ * D];
__device__ float  g_m[NSPLIT * NQ];
__device__ float  g_l[NSPLIT * NQ];

__device__ __forceinline__ uint32_t hx_smem_u32(const void* p) {
    uint32_t a;
    asm("{ .reg .u64 t; cvta.to.shared.u64 t, %1; cvt.u32.u64 %0, t; }" : "=r"(a) : "l"(p));
    return a;
}
__device__ __forceinline__ uint32_t hx_elect() {
    uint32_t p;
    asm volatile("{\n\t.reg .pred p;\n\telect.sync _|p, 0xFFFFFFFF;\n\t"
                 "selp.b32 %0, 1, 0, p;\n\t}" : "=r"(p));
    return p;
}
#define HX_TCALLOC(sa, n) \
    asm volatile("tcgen05.alloc.cta_group::1.sync.aligned.shared::cta.b32 [%0], %1;" \
                 :: "r"((uint32_t)(sa)), "r"((uint32_t)(n)) : "memory")
#define HX_TCDEALLOC(t, n) \
    asm volatile("tcgen05.dealloc.cta_group::1.sync.aligned.b32 %0, %1;" :: "r"(t), "r"(n))
#define HX_COMMIT(mb) \
    asm volatile("tcgen05.commit.cta_group::1.mbarrier::arrive::one.shared::cluster.b64 [%0];" \
                 :: "r"((uint32_t)(mb)) : "memory")
#define HX_FENCE_BEFORE() asm volatile("tcgen05.fence::before_thread_sync;" ::: "memory")
#define HX_FENCE_AFTER()  asm volatile("tcgen05.fence::after_thread_sync;" ::: "memory")
#define HX_WAIT_LD()      asm volatile("tcgen05.wait::ld.sync.aligned;" ::: "memory")
#define HX_FENCE_ASYNC()  asm volatile("fence.proxy.async.shared::cta;" ::: "memory")
#define HX_MBINIT(mb, c) \
    asm volatile("mbarrier.init.shared.b64 [%0], %1;" :: "r"((uint32_t)(mb)), "r"((uint32_t)(c)) : "memory")

#define HX_MBWAIT(mbaddr, ph) do {                                            \
    uint32_t _mb = (uint32_t)(mbaddr);                                        \
    uint32_t _pa = (uint32_t)(ph);                                            \
    uint32_t _done;                                                           \
    asm volatile("{\n\t.reg .pred p;\n\t"                                     \
        "mbarrier.try_wait.parity.acquire.cta.shared::cta.b64 p, [%1], %2;\n\t" \
        "selp.b32 %0, 1, 0, p;\n\t}" : "=r"(_done) : "r"(_mb), "r"(_pa) : "memory"); \
    if (!_done) {                                                             \
        asm volatile("{\n\t.reg .pred P1;\n\t"                                \
            "WL_%=:\n\t"                                                      \
            "mbarrier.try_wait.parity.acquire.cta.shared::cta.b64 P1, [%0], %1, 0x989680;\n\t" \
            "@P1 bra.uni WD_%=;\n\t"                                          \
            "bra.uni WL_%=;\n\t"                                              \
            "WD_%=:\n\t}" :: "r"(_mb), "r"(_pa) : "memory");                  \
    }                                                                         \
} while (0)

#define HX_CP16(dst, src) \
    asm volatile("cp.async.cg.shared.global [%0], [%1], 16;" \
                 :: "r"((uint32_t)(dst)), "l"(src) : "memory")
#define HX_CPCOMMIT() asm volatile("cp.async.commit_group;" ::: "memory")
#define HX_CPWAIT0()  asm volatile("cp.async.wait_group 0;" ::: "memory")
#define HX_CPWAIT1()  asm volatile("cp.async.wait_group 1;" ::: "memory")
#define HX_CPWAIT2()  asm volatile("cp.async.wait_group 2;" ::: "memory")

#define HX_LDTM_X32(r, addr) \
    asm volatile("tcgen05.ld.sync.aligned.32x32b.x32.b32 "                    \
        "{%0, %1, %2, %3, %4, %5, %6, %7, %8, %9, %10, %11, %12, %13, %14, %15, " \
        " %16, %17, %18, %19, %20, %21, %22, %23, %24, %25, %26, %27, %28, %29, %30, %31}, [%32];" \
        : "=r"((r)[0]),  "=r"((r)[1]),  "=r"((r)[2]),  "=r"((r)[3]),          \
          "=r"((r)[4]),  "=r"((r)[5]),  "=r"((r)[6]),  "=r"((r)[7]),          \
          "=r"((r)[8]),  "=r"((r)[9]),  "=r"((r)[10]), "=r"((r)[11]),         \
          "=r"((r)[12]), "=r"((r)[13]), "=r"((r)[14]), "=r"((r)[15]),         \
          "=r"((r)[16]), "=r"((r)[17]), "=r"((r)[18]), "=r"((r)[19]),         \
          "=r"((r)[20]), "=r"((r)[21]), "=r"((r)[22]), "=r"((r)[23]),         \
          "=r"((r)[24]), "=r"((r)[25]), "=r"((r)[26]), "=r"((r)[27]),         \
          "=r"((r)[28]), "=r"((r)[29]), "=r"((r)[30]), "=r"((r)[31])          \
        : "r"(addr))

__device__ __forceinline__ void hx_mma_f16_ss(uint32_t d, uint64_t a, uint64_t b,
                                              uint32_t idesc, uint32_t acc) {
#if HX_HAS_TCGEN05
    asm volatile("{\n\t.reg .pred p;\n\tsetp.ne.u32 p, %5, 0;\n\t"
        "tcgen05.mma.cta_group::1.kind::f16 [%0], %1, %2, %3, {%4, %4, %4, %4}, p;\n\t}"
        :: "r"(d), "l"(a), "l"(b), "r"(idesc), "r"(0u), "r"(acc) : "memory");
#endif
}

__device__ __forceinline__ uint64_t hx_desc_k(uint32_t sa) {
    return ((uint64_t)2 << 61) | ((uint64_t)1 << 46) | ((uint64_t)64 << 32) |
           ((uint64_t)1 << 16) | ((uint64_t)(sa >> 4) & 0x3FFF);
}

#define HX_IDESC_N64  0x08100010u
#define HX_IDESC_N128 0x08200010u

// tile offsets: 128r x 256B (2 atom cols x 16); 64r x 256B (2 x 8); 128r x 128B (1 x 16)
__device__ __forceinline__ uint32_t hx_offQ(int r, int c8) {
    uint32_t off = (uint32_t)((r >> 3) + ((c8 >> 3) << 4)) * 1024u +
                   (uint32_t)(r & 7) * 128u + (uint32_t)((c8 & 7) << 4);
    return off ^ ((off >> 3) & 0x70u);
}
__device__ __forceinline__ uint32_t hx_off64w(int r, int c8) {
    uint32_t off = (uint32_t)((r >> 3) + ((c8 >> 3) << 3)) * 1024u +
                   (uint32_t)(r & 7) * 128u + (uint32_t)((c8 & 7) << 4);
    return off ^ ((off >> 3) & 0x70u);
}
__device__ __forceinline__ uint32_t hx_off128n(int r, int c8) {
    uint32_t off = (uint32_t)(r >> 3) * 1024u + (uint32_t)(r & 7) * 128u + (uint32_t)(c8 << 4);
    return off ^ ((off >> 3) & 0x70u);
}
__device__ __forceinline__ uint64_t hx_koffQ(int k) {
    return (k < 4) ? (uint64_t)(k * 2) : (uint64_t)(1024 + (k - 4) * 2);
}
__device__ __forceinline__ uint64_t hx_koffK(int k) {
    return (k < 4) ? (uint64_t)(k * 2) : (uint64_t)(512 + (k - 4) * 2);
}

#define MB_QKD  8
#define MB_PVD  16
#define OFF_PART 128
#define OFF_RED  1280
#define OFF_QHI  2048
#define OFF_QLO  (OFF_QHI + 32768)
#define OFF_ST0  (OFF_QLO + 32768)     // 67584 (1024-aligned)
#define STB      65536
#define ST_KHI(s) (OFF_ST0 + (s) * STB)
#define ST_KLO(s) (ST_KHI(s) + 16384)
#define ST_KT(s)  (ST_KHI(s) + 32768)
#define ST_VT(s)  (ST_KHI(s) + 49152)
#define OFF_P     (OFF_ST0 + 2 * STB)  // 198656
#define SMEM_TOTAL (OFF_P + 16384)     // 215040 <= 232448

// TMEM: pass A S ping-pong 128 cols each (0..255); pass B S 64 cols each (0..127);
// OK 256..383, OV 384..511
#define TMA_S(s) (128 * (s))
#define TMB_S(s) (64 * (s))
#define TM_OK    256
#define TM_OV    384

__global__ void prep_hilo(const float* __restrict__ q, const float* __restrict__ k) {
    int i = blockIdx.x * blockDim.x + threadIdx.x;
    if (i < NKEYS * D) {
        float x = k[i];
        __half h = __float2half_rn(x);
        g_khi[i] = h;
        g_klo[i] = __float2half_rn(x - __half2float(h));
    }
    if (i < NQ * D) {
        float x = q[i];
        __half h = __float2half_rn(x);
        g_qhi[i] = h;
        g_qlo[i] = __float2half_rn(x - __half2float(h));
    }
}

__global__ void prep_transpose(const float* __restrict__ k, const float* __restrict__ v) {
    __shared__ __half sm[32][33];
    const float* src = blockIdx.z ? v : k;
    __half* dst = blockIdx.z ? g_vthi : g_kthi;
    int n0 = blockIdx.x * 32;
    int d0 = blockIdx.y * 32;
    #pragma unroll
    for (int yy = threadIdx.y; yy < 32; yy += 8)
        sm[yy][threadIdx.x] = __float2half_rn(src[(size_t)(n0 + yy) * D + d0 + threadIdx.x]);
    __syncthreads();
    #pragma unroll
    for (int yy = threadIdx.y; yy < 32; yy += 8)
        dst[(size_t)(d0 + yy) * NKEYS + n0 + threadIdx.x] = sm[threadIdx.x][yy];
}

__global__ __launch_bounds__(NTHREADS, 1) void flash_main() {
#if HX_HAS_TCGEN05
    extern __shared__ char smem[];
    uint32_t sb = hx_smem_u32(smem);
    int tid = threadIdx.x;
    int wid = tid >> 5;
    int lane = tid & 31;
    int colh = wid >> 2;                 // 0/1: column half handled by this warpgroup
    int row  = 32 * (wid & 3) + lane;    // TMEM lane / query row

    int split = blockIdx.x & (NSPLIT - 1);
    int q0 = (blockIdx.x >> 2) * 128;
    int n0 = split * KEYS_PER_SPLIT;

    if (wid == 0) HX_TCALLOC(sb, 512);
    if (tid == 0) { HX_MBINIT(sb + MB_QKD, 1); HX_MBINIT(sb + MB_PVD, 1); }
    __syncthreads();
    uint32_t tmem;
    asm volatile("ld.shared.b32 %0, [%1];" : "=r"(tmem) : "r"(sb));

    // persistent Q tiles (LDG+STS once)
    #pragma unroll
    for (int i = 0; i < 8; ++i) {
        int idx = tid + i * 256;
        int r = idx >> 4, c8 = idx & 15;
        size_t go = (size_t)(q0 + r) * D + (size_t)c8 * 8;
        *(uint4*)(smem + OFF_QHI + hx_offQ(r, c8)) = *(const uint4*)(g_qhi + go);
        *(uint4*)(smem + OFF_QLO + hx_offQ(r, c8)) = *(const uint4*)(g_qlo + go);
    }
    HX_FENCE_ASYNC();
    __syncthreads();

    uint64_t dqh = hx_desc_k(sb + OFF_QHI);
    uint64_t dql = hx_desc_k(sb + OFF_QLO);
    uint64_t dkh[2], dkl[2], dkt[2], dvt[2];
    #pragma unroll
    for (int s = 0; s < 2; ++s) {
        dkh[s] = hx_desc_k(sb + ST_KHI(s));
        dkl[s] = hx_desc_k(sb + ST_KLO(s));
        dkt[s] = hx_desc_k(sb + ST_KT(s));
        dvt[s] = hx_desc_k(sb + ST_VT(s));
    }
    uint64_t dpp = hx_desc_k(sb + OFF_P);
    uint32_t lead = (wid == 0) ? hx_elect() : 0;

    int phq = 0, php = 0;
    float m = -1e30f, lsum = 0.0f;

    // ======================= PASS A: row max (BNA=128) ======================
    // loadA(t) -> stage buffer: 128x256B blocked tile of khi
    #define LOADA(t, s_) do {                                                  \
        const __half* _src = g_khi + (size_t)(n0 + (t) * BNA) * D;             \
        _Pragma("unroll")                                                      \
        for (int _j = 0; _j < 8; ++_j) {                                       \
            int _idx = tid + _j * 256;                                         \
            int _r = _idx >> 4, _c8 = _idx & 15;                               \
            HX_CP16(sb + ST_KHI(s_) + hx_offQ(_r, _c8),                        \
                    _src + (size_t)_r * D + (size_t)_c8 * 8);                  \
        }                                                                      \
    } while (0)

    LOADA(0, 0); HX_CPCOMMIT();
    LOADA(1, 1); HX_CPCOMMIT();
    HX_CPWAIT1(); HX_FENCE_ASYNC(); __syncthreads();
    if (lead) {
        #pragma unroll
        for (int kk = 0; kk < 8; ++kk)
            hx_mma_f16_ss(tmem + TMA_S(0), dqh + hx_koffQ(kk),
                          dkh[0] + hx_koffQ(kk), HX_IDESC_N128, kk > 0);
        HX_COMMIT(sb + MB_QKD);
    }

    for (int t = 0; t < NTA; ++t) {
        int s = t & 1;
        HX_MBWAIT(sb + MB_QKD, phq); phq ^= 1;        // QK(t) done
        if (t + 2 < NTA) LOADA(t + 2, s);
        HX_CPCOMMIT();
        HX_CPWAIT1(); HX_FENCE_ASYNC(); __syncthreads();  // tile t+1 ready
        if (t + 1 < NTA && lead) {
            #pragma unroll
            for (int kk = 0; kk < 8; ++kk)
                hx_mma_f16_ss(tmem + TMA_S((t + 1) & 1), dqh + hx_koffQ(kk),
                              dkh[s ^ 1] + hx_koffQ(kk), HX_IDESC_N128, kk > 0);
            HX_COMMIT(sb + MB_QKD);
        }
        HX_FENCE_AFTER();
        uint32_t r0[32], r1[32];
        HX_LDTM_X32(r0, tmem + TMA_S(s) + 64 * colh);
        HX_LDTM_X32(r1, tmem + TMA_S(s) + 64 * colh + 32);
        HX_WAIT_LD();
        HX_FENCE_BEFORE();
        #pragma unroll
        for (int j = 0; j < 32; ++j) {
            m = fmaxf(m, __uint_as_float(r0[j]));
            m = fmaxf(m, __uint_as_float(r1[j]));
        }
    }
    HX_CPWAIT0();
    __syncthreads();

    {   // reduce m across column halves, broadcast per row
        float* part = (float*)(smem + OFF_PART);
        float* red  = (float*)(smem + OFF_RED);
        part[tid] = m;
        __syncthreads();
        if (tid < 128) red[tid] = fmaxf(part[tid], part[tid + 128]);
        __syncthreads();
        m = red[row];
        __syncthreads();
    }

    // ======================= PASS B: softmax + PV (BNB=64) ==================
    #define LOADB_KHILO(t, s_) do {                                            \
        size_t _nb = (size_t)(n0 + (t) * BNB);                                 \
        const __half* _skh = g_khi + _nb * D;                                  \
        const __half* _skl = g_klo + _nb * D;                                  \
        _Pragma("unroll")                                                      \
        for (int _j = 0; _j < 4; ++_j) {                                       \
            int _idx = tid + _j * 256;                                         \
            int _r = _idx >> 4, _c8 = _idx & 15;                               \
            uint32_t _so = hx_off64w(_r, _c8);                                 \
            size_t _go = (size_t)_r * D + (size_t)_c8 * 8;                     \
            HX_CP16(sb + ST_KHI(s_) + _so, _skh + _go);                        \
            HX_CP16(sb + ST_KLO(s_) + _so, _skl + _go);                        \
        }                                                                      \
    } while (0)
    #define LOADB_KTVT(t, s_) do {                                             \
        size_t _nb = (size_t)(n0 + (t) * BNB);                                 \
        const __half* _skt = g_kthi + _nb;                                     \
        const __half* _svt = g_vthi + _nb;                                     \
        _Pragma("unroll")                                                      \
        for (int _j = 0; _j < 4; ++_j) {                                       \
            int _idx = tid + _j * 256;                                         \
            int _r = _idx >> 3, _c8 = _idx & 7;                                \
            uint32_t _so = hx_off128n(_r, _c8);                                \
            size_t _go = (size_t)_r * NKEYS + (size_t)_c8 * 8;                 \
            HX_CP16(sb + ST_KT(s_) + _so, _skt + _go);                         \
            HX_CP16(sb + ST_VT(s_) + _so, _svt + _go);                         \
        }                                                                      \
    } while (0)

    LOADB_KHILO(0, 0); LOADB_KTVT(0, 0); HX_CPCOMMIT();
    LOADB_KHILO(1, 1); LOADB_KTVT(1, 1); HX_CPCOMMIT();
    HX_CPWAIT0(); HX_FENCE_ASYNC(); __syncthreads();
    if (lead) {
        #pragma unroll
        for (int kk = 0; kk < 8; ++kk)
            hx_mma_f16_ss(tmem + TMB_S(0), dqh + hx_koffQ(kk),
                          dkh[0] + hx_koffK(kk), HX_IDESC_N64, kk > 0);
        #pragma unroll
        for (int kk = 0; kk < 8; ++kk)
            hx_mma_f16_ss(tmem + TMB_S(0), dqh + hx_koffQ(kk),
                          dkl[0] + hx_koffK(kk), HX_IDESC_N64, 1u);
        #pragma unroll
        for (int kk = 0; kk < 8; ++kk)
            hx_mma_f16_ss(tmem + TMB_S(0), dql + hx_koffQ(kk),
                          dkh[0] + hx_koffK(kk), HX_IDESC_N64, 1u);
        HX_COMMIT(sb + MB_QKD);
    }

    for (int t = 0; t < NTB; ++t) {
        int s = t & 1;
        HX_MBWAIT(sb + MB_QKD, phq); phq ^= 1;        // QK(t) done -> khi/klo[s] free
        if (t + 2 < NTB) LOADB_KHILO(t + 2, s);
        HX_CPCOMMIT();                                 // group G1(t+2)
        HX_CPWAIT2(); HX_FENCE_ASYNC(); __syncthreads();  // forces G1(t+1), G2(t) done
        if (t + 1 < NTB && lead) {
            int s1 = s ^ 1;
            #pragma unroll
            for (int kk = 0; kk < 8; ++kk)
                hx_mma_f16_ss(tmem + TMB_S(s1), dqh + hx_koffQ(kk),
                              dkh[s1] + hx_koffK(kk), HX_IDESC_N64, kk > 0);
            #pragma unroll
            for (int kk = 0; kk < 8; ++kk)
                hx_mma_f16_ss(tmem + TMB_S(s1), dqh + hx_koffQ(kk),
                              dkl[s1] + hx_koffK(kk), HX_IDESC_N64, 1u);
            #pragma unroll
            for (int kk = 0; kk < 8; ++kk)
                hx_mma_f16_ss(tmem + TMB_S(s1), dql + hx_koffQ(kk),
                              dkh[s1] + hx_koffK(kk), HX_IDESC_N64, 1u);
            HX_COMMIT(sb + MB_QKD);
        }
        // softmax(t) on S[s] (overlaps QK(t+1))
        HX_FENCE_AFTER();
        uint32_t r[32];
        HX_LDTM_X32(r, tmem + TMB_S(s) + 32 * colh);
        HX_WAIT_LD();
        HX_FENCE_BEFORE();
        #pragma unroll
        for (int u = 0; u < 4; ++u) {
            uint32_t h2[4];
            #pragma unroll
            for (int j = 0; j < 4; ++j) {
                float p0 = __expf(__uint_as_float(r[8 * u + 2 * j])     - m);
                float p1 = __expf(__uint_as_float(r[8 * u + 2 * j + 1]) - m);
                lsum += p0 + p1;
                __half2 hh = __floats2half2_rn(p0, p1);
                h2[j] = *(uint32_t*)&hh;
            }
            *(uint4*)(smem + OFF_P + hx_off128n(row, 4 * colh + u)) =
                make_uint4(h2[0], h2[1], h2[2], h2[3]);
        }
        HX_FENCE_ASYNC();
        __syncthreads();
        if (lead) {
            #pragma unroll
            for (int kk = 0; kk < 4; ++kk) {
                uint32_t acc = (t > 0 || kk > 0) ? 1u : 0u;
                hx_mma_f16_ss(tmem + TM_OK, dpp + 2 * kk, dkt[s] + 2 * kk,
                              HX_IDESC_N128, acc);
                hx_mma_f16_ss(tmem + TM_OV, dpp + 2 * kk, dvt[s] + 2 * kk,
                              HX_IDESC_N128, acc);
            }
            HX_COMMIT(sb + MB_PVD);
        }
        HX_MBWAIT(sb + MB_PVD, php); php ^= 1;        // PV(t) done -> kt/vt[s], P free
        if (t + 2 < NTB) LOADB_KTVT(t + 2, s);
        HX_CPCOMMIT();                                 // group G2(t+2)
    }
    HX_CPWAIT0();
    __syncthreads();

    // ======================= epilogue ========================================
    {
        float* part = (float*)(smem + OFF_PART);
        float* red  = (float*)(smem + OFF_RED);
        part[tid] = lsum;
        __syncthreads();
        if (tid < 128) {
            red[tid] = part[tid] + part[tid + 128];
            g_m[split * NQ + q0 + tid] = m;
            g_l[split * NQ + q0 + tid] = red[tid];
        }
    }
    HX_FENCE_AFTER();
    size_t base = ((size_t)split * NQ + q0 + row) * D + 64 * colh;
    #pragma unroll
    for (int c = 0; c < 2; ++c) {
        uint32_t rk[32];
        HX_LDTM_X32(rk, tmem + TM_OK + 64 * colh + 32 * c);
        HX_WAIT_LD();
        #pragma unroll
        for (int j = 0; j < 32; ++j)
            g_ok[base + 32 * c + j] = __uint_as_float(rk[j]);
    }
    #pragma unroll
    for (int c = 0; c < 2; ++c) {
        uint32_t rv[32];
        HX_LDTM_X32(rv, tmem + TM_OV + 64 * colh + 32 * c);
        HX_WAIT_LD();
        #pragma unroll
        for (int j = 0; j < 32; ++j)
            g_ov[base + 32 * c + j] = __uint_as_float(rv[j]);
    }
    HX_FENCE_BEFORE();
    __syncthreads();
    if (wid == 0) HX_TCDEALLOC(tmem, 512);
#endif
}

__global__ void reduce_kernel(float* __restrict__ out) {
    int q = blockIdx.x;
    int d = threadIdx.x;
    float m0 = g_m[q], m1 = g_m[NQ + q], m2 = g_m[2 * NQ + q], m3 = g_m[3 * NQ + q];
    float ms = fmaxf(fmaxf(m0, m1), fmaxf(m2, m3));
    float w0 = __expf(m0 - ms), w1 = __expf(m1 - ms);
    float w2 = __expf(m2 - ms), w3 = __expf(m3 - ms);
    float inv = 1.0f / (g_l[q] * w0 + g_l[NQ + q] * w1 +
                        g_l[2 * NQ + q] * w2 + g_l[3 * NQ + q] * w3);
    size_t i0 = (size_t)q * D + d;
    size_t i1 = ((size_t)NQ + q) * D + d;
    size_t i2 = ((size_t)2 * NQ + q) * D + d;
    size_t i3 = ((size_t)3 * NQ + q) * D + d;
    float ok = g_ok[i0] * w0 + g_ok[i1] * w1 + g_ok[i2] * w2 + g_ok[i3] * w3;
    float ov = g_ov[i0] * w0 + g_ov[i1] * w1 + g_ov[i2] * w2 + g_ov[i3] * w3;
    out[(size_t)q * D + d] = ok * inv;
    out[(size_t)NQ * D + (size_t)q * D + d] = ov * inv;
}

extern "C" void kernel_launch(void* const* d_in, const int* in_sizes, int n_in,
                              void* d_out, int out_size) {
    const float* q = (const float*)d_in[0];
    const float* k = (const float*)d_in[1];
    const float* v = (const float*)d_in[2];
    float* out = (float*)d_out;
    (void)in_sizes; (void)n_in; (void)out_size;

    cudaFuncSetAttribute(flash_main, cudaFuncAttributeMaxDynamicSharedMemorySize, SMEM_TOTAL);
    prep_hilo<<<(NKEYS * D) / 256, 256>>>(q, k);
    dim3 gt(NKEYS / 32, D / 32, 2), bt(32, 8);
    prep_transpose<<<gt, bt>>>(k, v);
    flash_main<<<NCTA, NTHREADS, SMEM_TOTAL>>>();
    reduce_kernel<<<NQ, 128>>>(out);
}

// round 7
// speedup vs baseline: 2.4917x; 1.1313x over previous
#include <cuda_runtime.h>
#include <cuda_fp16.h>
#include <cstdint>

#if defined(__CUDA_ARCH_FEAT_SM103_ALL) || defined(__CUDA_ARCH_FEAT_SM100_ALL)
#define HX_HAS_TCGEN05 1
#else
#define HX_HAS_TCGEN05 0
#endif

#define D        128
#define NQ       4096
#define NKEYS    65536
#define NSPLIT   4
#define KEYS_PER_SPLIT (NKEYS / NSPLIT)
#define BNA      128
#define NTA      (KEYS_PER_SPLIT / BNA)   // 128
#define BNB      64
#define NTB      (KEYS_PER_SPLIT / BNB)   // 256
#define NCTA     128
#define NTHREADS 256

__device__ __half g_qhi[NQ * D];
__device__ __half g_qlo[NQ * D];
__device__ __half g_khi[(size_t)NKEYS * D];
__device__ __half g_klo[(size_t)NKEYS * D];
__device__ __half g_kthi[(size_t)D * NKEYS];   // [d][n]
__device__ __half g_vthi[(size_t)D * NKEYS];   // [d][n]
__device__ float  g_ok[(size_t)NSPLIT * NQ * D];
__device__ float  g_ov[(size_t)NSPLIT * NQ * D];
__device__ float  g_m[NSPLIT * NQ];
__device__ float  g_l[NSPLIT * NQ];

__device__ __forceinline__ uint32_t hx_smem_u32(const void* p) {
    uint32_t a;
    asm("{ .reg .u64 t; cvta.to.shared.u64 t, %1; cvt.u32.u64 %0, t; }" : "=r"(a) : "l"(p));
    return a;
}
__device__ __forceinline__ uint32_t hx_elect() {
    uint32_t p;
    asm volatile("{\n\t.reg .pred p;\n\telect.sync _|p, 0xFFFFFFFF;\n\t"
                 "selp.b32 %0, 1, 0, p;\n\t}" : "=r"(p));
    return p;
}
#define HX_TCALLOC(sa, n) \
    asm volatile("tcgen05.alloc.cta_group::1.sync.aligned.shared::cta.b32 [%0], %1;" \
                 :: "r"((uint32_t)(sa)), "r"((uint32_t)(n)) : "memory")
#define HX_TCDEALLOC(t, n) \
    asm volatile("tcgen05.dealloc.cta_group::1.sync.aligned.b32 %0, %1;" :: "r"(t), "r"(n))
#define HX_COMMIT(mb) \
    asm volatile("tcgen05.commit.cta_group::1.mbarrier::arrive::one.shared::cluster.b64 [%0];" \
                 :: "r"((uint32_t)(mb)) : "memory")
#define HX_FENCE_BEFORE() asm volatile("tcgen05.fence::before_thread_sync;" ::: "memory")
#define HX_FENCE_AFTER()  asm volatile("tcgen05.fence::after_thread_sync;" ::: "memory")
#define HX_WAIT_LD()      asm volatile("tcgen05.wait::ld.sync.aligned;" ::: "memory")
#define HX_FENCE_ASYNC()  asm volatile("fence.proxy.async.shared::cta;" ::: "memory")
#define HX_MBINIT(mb, c) \
    asm volatile("mbarrier.init.shared.b64 [%0], %1;" :: "r"((uint32_t)(mb)), "r"((uint32_t)(c)) : "memory")

#define HX_MBWAIT(mbaddr, ph) do {                                            \
    uint32_t _mb = (uint32_t)(mbaddr);                                        \
    uint32_t _pa = (uint32_t)(ph);                                            \
    uint32_t _done;                                                           \
    asm volatile("{\n\t.reg .pred p;\n\t"                                     \
        "mbarrier.try_wait.parity.acquire.cta.shared::cta.b64 p, [%1], %2;\n\t" \
        "selp.b32 %0, 1, 0, p;\n\t}" : "=r"(_done) : "r"(_mb), "r"(_pa) : "memory"); \
    if (!_done) {                                                             \
        asm volatile("{\n\t.reg .pred P1;\n\t"                                \
            "WL_%=:\n\t"                                                      \
            "mbarrier.try_wait.parity.acquire.cta.shared::cta.b64 P1, [%0], %1, 0x989680;\n\t" \
            "@P1 bra.uni WD_%=;\n\t"                                          \
            "bra.uni WL_%=;\n\t"                                              \
            "WD_%=:\n\t}" :: "r"(_mb), "r"(_pa) : "memory");                  \
    }                                                                         \
} while (0)

#define HX_CP16(dst, src) \
    asm volatile("cp.async.cg.shared.global [%0], [%1], 16;" \
                 :: "r"((uint32_t)(dst)), "l"(src) : "memory")
#define HX_CPCOMMIT() asm volatile("cp.async.commit_group;" ::: "memory")
#define HX_CPWAIT0()  asm volatile("cp.async.wait_group 0;" ::: "memory")
#define HX_CPWAIT1()  asm volatile("cp.async.wait_group 1;" ::: "memory")
#define HX_CPWAIT2()  asm volatile("cp.async.wait_group 2;" ::: "memory")

#define HX_LDTM_X32(r, addr) \
    asm volatile("tcgen05.ld.sync.aligned.32x32b.x32.b32 "                    \
        "{%0, %1, %2, %3, %4, %5, %6, %7, %8, %9, %10, %11, %12, %13, %14, %15, " \
        " %16, %17, %18, %19, %20, %21, %22, %23, %24, %25, %26, %27, %28, %29, %30, %31}, [%32];" \
        : "=r"((r)[0]),  "=r"((r)[1]),  "=r"((r)[2]),  "=r"((r)[3]),          \
          "=r"((r)[4]),  "=r"((r)[5]),  "=r"((r)[6]),  "=r"((r)[7]),          \
          "=r"((r)[8]),  "=r"((r)[9]),  "=r"((r)[10]), "=r"((r)[11]),         \
          "=r"((r)[12]), "=r"((r)[13]), "=r"((r)[14]), "=r"((r)[15]),         \
          "=r"((r)[16]), "=r"((r)[17]), "=r"((r)[18]), "=r"((r)[19]),         \
          "=r"((r)[20]), "=r"((r)[21]), "=r"((r)[22]), "=r"((r)[23]),         \
          "=r"((r)[24]), "=r"((r)[25]), "=r"((r)[26]), "=r"((r)[27]),         \
          "=r"((r)[28]), "=r"((r)[29]), "=r"((r)[30]), "=r"((r)[31])          \
        : "r"(addr))

__device__ __forceinline__ void hx_mma_f16_ss(uint32_t d, uint64_t a, uint64_t b,
                                              uint32_t idesc, uint32_t acc) {
#if HX_HAS_TCGEN05
    asm volatile("{\n\t.reg .pred p;\n\tsetp.ne.u32 p, %5, 0;\n\t"
        "tcgen05.mma.cta_group::1.kind::f16 [%0], %1, %2, %3, {%4, %4, %4, %4}, p;\n\t}"
        :: "r"(d), "l"(a), "l"(b), "r"(idesc), "r"(0u), "r"(acc) : "memory");
#endif
}

__device__ __forceinline__ uint64_t hx_desc_k(uint32_t sa) {
    return ((uint64_t)2 << 61) | ((uint64_t)1 << 46) | ((uint64_t)64 << 32) |
           ((uint64_t)1 << 16) | ((uint64_t)(sa >> 4) & 0x3FFF);
}

#define HX_IDESC_N64  0x08100010u
#define HX_IDESC_N128 0x08200010u

__device__ __forceinline__ uint32_t hx_offQ(int r, int c8) {
    uint32_t off = (uint32_t)((r >> 3) + ((c8 >> 3) << 4)) * 1024u +
                   (uint32_t)(r & 7) * 128u + (uint32_t)((c8 & 7) << 4);
    return off ^ ((off >> 3) & 0x70u);
}
__device__ __forceinline__ uint32_t hx_off64w(int r, int c8) {
    uint32_t off = (uint32_t)((r >> 3) + ((c8 >> 3) << 3)) * 1024u +
                   (uint32_t)(r & 7) * 128u + (uint32_t)((c8 & 7) << 4);
    return off ^ ((off >> 3) & 0x70u);
}
__device__ __forceinline__ uint32_t hx_off128n(int r, int c8) {
    uint32_t off = (uint32_t)(r >> 3) * 1024u + (uint32_t)(r & 7) * 128u + (uint32_t)(c8 << 4);
    return off ^ ((off >> 3) & 0x70u);
}
__device__ __forceinline__ uint64_t hx_koffQ(int k) {
    return (k < 4) ? (uint64_t)(k * 2) : (uint64_t)(1024 + (k - 4) * 2);
}
__device__ __forceinline__ uint64_t hx_koffK(int k) {
    return (k < 4) ? (uint64_t)(k * 2) : (uint64_t)(512 + (k - 4) * 2);
}

#define MB_QKD  8
#define MB_PVD  16
#define OFF_PART 128
#define OFF_RED  1280
#define OFF_QHI  2048
#define OFF_QLO  (OFF_QHI + 32768)
#define OFF_ST0  (OFF_QLO + 32768)     // 67584 (1024-aligned)
#define STB      65536
#define ST_KHI(s) (OFF_ST0 + (s) * STB)
#define ST_KLO(s) (ST_KHI(s) + 16384)
#define ST_KT(s)  (ST_KHI(s) + 32768)
#define ST_VT(s)  (ST_KHI(s) + 49152)
#define OFF_P(s)  (OFF_ST0 + 2 * STB + 16384 * (s))   // 198656 / 215040
#define SMEM_TOTAL (OFF_ST0 + 2 * STB + 32768)        // 231424 <= 232448

#define TMA_S(s) (128 * (s))
#define TMB_S(s) (64 * (s))
#define TM_OK    256
#define TM_OV    384

__global__ void prep_hilo(const float* __restrict__ q, const float* __restrict__ k) {
    int i = blockIdx.x * blockDim.x + threadIdx.x;
    if (i < NKEYS * D) {
        float x = k[i];
        __half h = __float2half_rn(x);
        g_khi[i] = h;
        g_klo[i] = __float2half_rn(x - __half2float(h));
    }
    if (i < NQ * D) {
        float x = q[i];
        __half h = __float2half_rn(x);
        g_qhi[i] = h;
        g_qlo[i] = __float2half_rn(x - __half2float(h));
    }
}

__global__ void prep_transpose(const float* __restrict__ k, const float* __restrict__ v) {
    __shared__ __half sm[32][33];
    const float* src = blockIdx.z ? v : k;
    __half* dst = blockIdx.z ? g_vthi : g_kthi;
    int n0 = blockIdx.x * 32;
    int d0 = blockIdx.y * 32;
    #pragma unroll
    for (int yy = threadIdx.y; yy < 32; yy += 8)
        sm[yy][threadIdx.x] = __float2half_rn(src[(size_t)(n0 + yy) * D + d0 + threadIdx.x]);
    __syncthreads();
    #pragma unroll
    for (int yy = threadIdx.y; yy < 32; yy += 8)
        dst[(size_t)(d0 + yy) * NKEYS + n0 + threadIdx.x] = sm[threadIdx.x][yy];
}

__global__ __launch_bounds__(NTHREADS, 1) void flash_main() {
#if HX_HAS_TCGEN05
    extern __shared__ char smem[];
    uint32_t sb = hx_smem_u32(smem);
    int tid = threadIdx.x;
    int wid = tid >> 5;
    int lane = tid & 31;
    int colh = wid >> 2;
    int row  = 32 * (wid & 3) + lane;

    int split = blockIdx.x & (NSPLIT - 1);
    int q0 = (blockIdx.x >> 2) * 128;
    int n0 = split * KEYS_PER_SPLIT;

    if (wid == 0) HX_TCALLOC(sb, 512);
    if (tid == 0) { HX_MBINIT(sb + MB_QKD, 1); HX_MBINIT(sb + MB_PVD, 1); }
    __syncthreads();
    uint32_t tmem;
    asm volatile("ld.shared.b32 %0, [%1];" : "=r"(tmem) : "r"(sb));

    #pragma unroll
    for (int i = 0; i < 8; ++i) {
        int idx = tid + i * 256;
        int r = idx >> 4, c8 = idx & 15;
        size_t go = (size_t)(q0 + r) * D + (size_t)c8 * 8;
        *(uint4*)(smem + OFF_QHI + hx_offQ(r, c8)) = *(const uint4*)(g_qhi + go);
        *(uint4*)(smem + OFF_QLO + hx_offQ(r, c8)) = *(const uint4*)(g_qlo + go);
    }
    HX_FENCE_ASYNC();
    __syncthreads();

    uint64_t dqh = hx_desc_k(sb + OFF_QHI);
    uint64_t dql = hx_desc_k(sb + OFF_QLO);
    uint64_t dkh[2], dkl[2], dkt[2], dvt[2], dpp[2];
    #pragma unroll
    for (int s = 0; s < 2; ++s) {
        dkh[s] = hx_desc_k(sb + ST_KHI(s));
        dkl[s] = hx_desc_k(sb + ST_KLO(s));
        dkt[s] = hx_desc_k(sb + ST_KT(s));
        dvt[s] = hx_desc_k(sb + ST_VT(s));
        dpp[s] = hx_desc_k(sb + OFF_P(s));
    }
    uint32_t lead = (wid == 0) ? hx_elect() : 0;

    int phq = 0, php = 0;
    float m = -1e30f, lsum = 0.0f;

    // ======================= PASS A: row max (BNA=128) ======================
    #define LOADA(t, s_) do {                                                  \
        const __half* _src = g_khi + (size_t)(n0 + (t) * BNA) * D;             \
        _Pragma("unroll")                                                      \
        for (int _j = 0; _j < 8; ++_j) {                                       \
            int _idx = tid + _j * 256;                                         \
            int _r = _idx >> 4, _c8 = _idx & 15;                               \
            HX_CP16(sb + ST_KHI(s_) + hx_offQ(_r, _c8),                        \
                    _src + (size_t)_r * D + (size_t)_c8 * 8);                  \
        }                                                                      \
    } while (0)

    LOADA(0, 0); HX_CPCOMMIT();
    LOADA(1, 1); HX_CPCOMMIT();
    HX_CPWAIT1(); HX_FENCE_ASYNC(); __syncthreads();
    if (lead) {
        #pragma unroll
        for (int kk = 0; kk < 8; ++kk)
            hx_mma_f16_ss(tmem + TMA_S(0), dqh + hx_koffQ(kk),
                          dkh[0] + hx_koffQ(kk), HX_IDESC_N128, kk > 0);
        HX_COMMIT(sb + MB_QKD);
    }

    for (int t = 0; t < NTA; ++t) {
        int s = t & 1;
        HX_MBWAIT(sb + MB_QKD, phq); phq ^= 1;
        if (t + 2 < NTA) LOADA(t + 2, s);
        HX_CPCOMMIT();
        HX_CPWAIT1(); HX_FENCE_ASYNC(); __syncthreads();
        if (t + 1 < NTA && lead) {
            #pragma unroll
            for (int kk = 0; kk < 8; ++kk)
                hx_mma_f16_ss(tmem + TMA_S((t + 1) & 1), dqh + hx_koffQ(kk),
                              dkh[s ^ 1] + hx_koffQ(kk), HX_IDESC_N128, kk > 0);
            HX_COMMIT(sb + MB_QKD);
        }
        HX_FENCE_AFTER();
        uint32_t r0[32], r1[32];
        HX_LDTM_X32(r0, tmem + TMA_S(s) + 64 * colh);
        HX_LDTM_X32(r1, tmem + TMA_S(s) + 64 * colh + 32);
        HX_WAIT_LD();
        HX_FENCE_BEFORE();
        #pragma unroll
        for (int j = 0; j < 32; ++j) {
            m = fmaxf(m, __uint_as_float(r0[j]));
            m = fmaxf(m, __uint_as_float(r1[j]));
        }
    }
    HX_CPWAIT0();
    __syncthreads();

    {
        float* part = (float*)(smem + OFF_PART);
        float* red  = (float*)(smem + OFF_RED);
        part[tid] = m;
        __syncthreads();
        if (tid < 128) red[tid] = fmaxf(part[tid], part[tid + 128]);
        __syncthreads();
        m = red[row];
        __syncthreads();
    }

    // ======================= PASS B: softmax + PV (BNB=64) ==================
    #define LOADB_KHILO(t, s_) do {                                            \
        size_t _nb = (size_t)(n0 + (t) * BNB);                                 \
        const __half* _skh = g_khi + _nb * D;                                  \
        const __half* _skl = g_klo + _nb * D;                                  \
        _Pragma("unroll")                                                      \
        for (int _j = 0; _j < 4; ++_j) {                                       \
            int _idx = tid + _j * 256;                                         \
            int _r = _idx >> 4, _c8 = _idx & 15;                               \
            uint32_t _so = hx_off64w(_r, _c8);                                 \
            size_t _go = (size_t)_r * D + (size_t)_c8 * 8;                     \
            HX_CP16(sb + ST_KHI(s_) + _so, _skh + _go);                        \
            HX_CP16(sb + ST_KLO(s_) + _so, _skl + _go);                        \
        }                                                                      \
    } while (0)
    #define LOADB_KTVT(t, s_) do {                                             \
        size_t _nb = (size_t)(n0 + (t) * BNB);                                 \
        const __half* _skt = g_kthi + _nb;                                     \
        const __half* _svt = g_vthi + _nb;                                     \
        _Pragma("unroll")                                                      \
        for (int _j = 0; _j < 4; ++_j) {                                       \
            int _idx = tid + _j * 256;                                         \
            int _r = _idx >> 3, _c8 = _idx & 7;                                \
            uint32_t _so = hx_off128n(_r, _c8);                                \
            size_t _go = (size_t)_r * NKEYS + (size_t)_c8 * 8;                 \
            HX_CP16(sb + ST_KT(s_) + _so, _skt + _go);                         \
            HX_CP16(sb + ST_VT(s_) + _so, _svt + _go);                         \
        }                                                                      \
    } while (0)

    // preamble: tile 0 fully, khilo of tile 1
    LOADB_KHILO(0, 0); LOADB_KTVT(0, 0); HX_CPCOMMIT();
    LOADB_KHILO(1, 1); HX_CPCOMMIT();
    HX_CPWAIT1(); HX_FENCE_ASYNC(); __syncthreads();
    if (lead) {
        #pragma unroll
        for (int kk = 0; kk < 8; ++kk)
            hx_mma_f16_ss(tmem + TMB_S(0), dqh + hx_koffQ(kk),
                          dkh[0] + hx_koffK(kk), HX_IDESC_N64, kk > 0);
        #pragma unroll
        for (int kk = 0; kk < 8; ++kk)
            hx_mma_f16_ss(tmem + TMB_S(0), dqh + hx_koffQ(kk),
                          dkl[0] + hx_koffK(kk), HX_IDESC_N64, 1u);
        #pragma unroll
        for (int kk = 0; kk < 8; ++kk)
            hx_mma_f16_ss(tmem + TMB_S(0), dql + hx_koffQ(kk),
                          dkh[0] + hx_koffK(kk), HX_IDESC_N64, 1u);
        HX_COMMIT(sb + MB_QKD);
    }

    for (int t = 0; t < NTB; ++t) {
        int s = t & 1;
        HX_MBWAIT(sb + MB_QKD, phq); phq ^= 1;          // QK(t) done
        if (t + 2 < NTB) LOADB_KHILO(t + 2, s);         // khi/klo[s] free
        HX_CPCOMMIT();
        if (t >= 1) { HX_MBWAIT(sb + MB_PVD, php); php ^= 1; }  // PV(t-1) done
        if (t + 1 < NTB) LOADB_KTVT(t + 1, s ^ 1);      // kt/vt[s^1] free
        HX_CPCOMMIT();
        HX_CPWAIT2(); HX_FENCE_ASYNC(); __syncthreads(); // khilo(t+1), ktvt(t) ready
        if (t + 1 < NTB && lead) {
            int s1 = s ^ 1;
            #pragma unroll
            for (int kk = 0; kk < 8; ++kk)
                hx_mma_f16_ss(tmem + TMB_S(s1), dqh + hx_koffQ(kk),
                              dkh[s1] + hx_koffK(kk), HX_IDESC_N64, kk > 0);
            #pragma unroll
            for (int kk = 0; kk < 8; ++kk)
                hx_mma_f16_ss(tmem + TMB_S(s1), dqh + hx_koffQ(kk),
                              dkl[s1] + hx_koffK(kk), HX_IDESC_N64, 1u);
            #pragma unroll
            for (int kk = 0; kk < 8; ++kk)
                hx_mma_f16_ss(tmem + TMB_S(s1), dql + hx_koffQ(kk),
                              dkh[s1] + hx_koffK(kk), HX_IDESC_N64, 1u);
            HX_COMMIT(sb + MB_QKD);
        }
        // softmax(t): S[s] -> P[s]   (overlaps QK(t+1))
        HX_FENCE_AFTER();
        uint32_t r[32];
        HX_LDTM_X32(r, tmem + TMB_S(s) + 32 * colh);
        HX_WAIT_LD();
        HX_FENCE_BEFORE();
        #pragma unroll
        for (int u = 0; u < 4; ++u) {
            uint32_t h2[4];
            #pragma unroll
            for (int j = 0; j < 4; ++j) {
                float p0 = __expf(__uint_as_float(r[8 * u + 2 * j])     - m);
                float p1 = __expf(__uint_as_float(r[8 * u + 2 * j + 1]) - m);
                lsum += p0 + p1;
                __half2 hh = __floats2half2_rn(p0, p1);
                h2[j] = *(uint32_t*)&hh;
            }
            *(uint4*)(smem + OFF_P(s) + hx_off128n(row, 4 * colh + u)) =
                make_uint4(h2[0], h2[1], h2[2], h2[3]);
        }
        HX_FENCE_ASYNC();
        __syncthreads();
        if (lead) {                                      // PV(t): overlaps next iter
            #pragma unroll
            for (int kk = 0; kk < 4; ++kk) {
                uint32_t acc = (t > 0 || kk > 0) ? 1u : 0u;
                hx_mma_f16_ss(tmem + TM_OK, dpp[s] + 2 * kk, dkt[s] + 2 * kk,
                              HX_IDESC_N128, acc);
                hx_mma_f16_ss(tmem + TM_OV, dpp[s] + 2 * kk, dvt[s] + 2 * kk,
                              HX_IDESC_N128, acc);
            }
            HX_COMMIT(sb + MB_PVD);
        }
    }
    HX_MBWAIT(sb + MB_PVD, php); php ^= 1;               // final PV done
    HX_CPWAIT0();
    __syncthreads();

    // ======================= epilogue ========================================
    {
        float* part = (float*)(smem + OFF_PART);
        float* red  = (float*)(smem + OFF_RED);
        part[tid] = lsum;
        __syncthreads();
        if (tid < 128) {
            red[tid] = part[tid] + part[tid + 128];
            g_m[split * NQ + q0 + tid] = m;
            g_l[split * NQ + q0 + tid] = red[tid];
        }
    }
    HX_FENCE_AFTER();
    size_t base = ((size_t)split * NQ + q0 + row) * D + 64 * colh;
    #pragma unroll
    for (int c = 0; c < 2; ++c) {
        uint32_t rk[32];
        HX_LDTM_X32(rk, tmem + TM_OK + 64 * colh + 32 * c);
        HX_WAIT_LD();
        #pragma unroll
        for (int j = 0; j < 32; ++j)
            g_ok[base + 32 * c + j] = __uint_as_float(rk[j]);
    }
    #pragma unroll
    for (int c = 0; c < 2; ++c) {
        uint32_t rv[32];
        HX_LDTM_X32(rv, tmem + TM_OV + 64 * colh + 32 * c);
        HX_WAIT_LD();
        #pragma unroll
        for (int j = 0; j < 32; ++j)
            g_ov[base + 32 * c + j] = __uint_as_float(rv[j]);
    }
    HX_FENCE_BEFORE();
    __syncthreads();
    if (wid == 0) HX_TCDEALLOC(tmem, 512);
#endif
}

__global__ void reduce_kernel(float* __restrict__ out) {
    int q = blockIdx.x;
    int d = threadIdx.x;
    float m0 = g_m[q], m1 = g_m[NQ + q], m2 = g_m[2 * NQ + q], m3 = g_m[3 * NQ + q];
    float ms = fmaxf(fmaxf(m0, m1), fmaxf(m2, m3));
    float w0 = __expf(m0 - ms), w1 = __expf(m1 - ms);
    float w2 = __expf(m2 - ms), w3 = __expf(m3 - ms);
    float inv = 1.0f / (g_l[q] * w0 + g_l[NQ + q] * w1 +
                        g_l[2 * NQ + q] * w2 + g_l[3 * NQ + q] * w3);
    size_t i0 = (size_t)q * D + d;
    size_t i1 = ((size_t)NQ + q) * D + d;
    size_t i2 = ((size_t)2 * NQ + q) * D + d;
    size_t i3 = ((size_t)3 * NQ + q) * D + d;
    float ok = g_ok[i0] * w0 + g_ok[i1] * w1 + g_ok[i2] * w2 + g_ok[i3] * w3;
    float ov = g_ov[i0] * w0 + g_ov[i1] * w1 + g_ov[i2] * w2 + g_ov[i3] * w3;
    out[(size_t)q * D + d] = ok * inv;
    out[(size_t)NQ * D + (size_t)q * D + d] = ov * inv;
}

extern "C" void kernel_launch(void* const* d_in, const int* in_sizes, int n_in,
                              void* d_out, int out_size) {
    const float* q = (const float*)d_in[0];
    const float* k = (const float*)d_in[1];
    const float* v = (const float*)d_in[2];
    float* out = (float*)d_out;
    (void)in_sizes; (void)n_in; (void)out_size;

    cudaFuncSetAttribute(flash_main, cudaFuncAttributeMaxDynamicSharedMemorySize, SMEM_TOTAL);
    prep_hilo<<<(NKEYS * D) / 256, 256>>>(q, k);
    dim3 gt(NKEYS / 32, D / 32, 2), bt(32, 8);
    prep_transpose<<<gt, bt>>>(k, v);
    flash_main<<<NCTA, NTHREADS, SMEM_TOTAL>>>();
    reduce_kernel<<<NQ, 128>>>(out);
}

// round 10
// speedup vs baseline: 2.5589x; 1.0269x over previous
#include <cuda_runtime.h>
#include <cuda_fp16.h>
#include <cstdint>

#if defined(__CUDA_ARCH_FEAT_SM103_ALL) || defined(__CUDA_ARCH_FEAT_SM100_ALL)
#define HX_HAS_TCGEN05 1
#else
#define HX_HAS_TCGEN05 0
#endif

#define D        128
#define NQ       4096
#define NKEYS    65536
#define NSPLIT   4
#define KEYS_PER_SPLIT (NKEYS / NSPLIT)
#define BNA      256
#define NTA      (KEYS_PER_SPLIT / BNA)   // 64
#define BNB      64
#define NTB      (KEYS_PER_SPLIT / BNB)   // 256
#define NCTA     128
#define NTHREADS 256

__device__ __half g_qhi[NQ * D];
__device__ __half g_qlo[NQ * D];
__device__ __half g_khi[(size_t)NKEYS * D];
__device__ __half g_klo[(size_t)NKEYS * D];
__device__ __half g_kthi[(size_t)D * NKEYS];   // [d][n]
__device__ __half g_vthi[(size_t)D * NKEYS];   // [d][n]
__device__ float  g_ok[(size_t)NSPLIT * NQ * D];
__device__ float  g_ov[(size_t)NSPLIT * NQ * D];
__device__ float  g_m[NSPLIT * NQ];
__device__ float  g_l[NSPLIT * NQ];

__device__ __forceinline__ uint32_t hx_smem_u32(const void* p) {
    uint32_t a;
    asm("{ .reg .u64 t; cvta.to.shared.u64 t, %1; cvt.u32.u64 %0, t; }" : "=r"(a) : "l"(p));
    return a;
}
__device__ __forceinline__ uint32_t hx_elect() {
    uint32_t p;
    asm volatile("{\n\t.reg .pred p;\n\telect.sync _|p, 0xFFFFFFFF;\n\t"
                 "selp.b32 %0, 1, 0, p;\n\t}" : "=r"(p));
    return p;
}
#define HX_TCALLOC(sa, n) \
    asm volatile("tcgen05.alloc.cta_group::1.sync.aligned.shared::cta.b32 [%0], %1;" \
                 :: "r"((uint32_t)(sa)), "r"((uint32_t)(n)) : "memory")
#define HX_TCDEALLOC(t, n) \
    asm volatile("tcgen05.dealloc.cta_group::1.sync.aligned.b32 %0, %1;" :: "r"(t), "r"(n))
#define HX_COMMIT(mb) \
    asm volatile("tcgen05.commit.cta_group::1.mbarrier::arrive::one.shared::cluster.b64 [%0];" \
                 :: "r"((uint32_t)(mb)) : "memory")
#define HX_FENCE_BEFORE() asm volatile("tcgen05.fence::before_thread_sync;" ::: "memory")
#define HX_FENCE_AFTER()  asm volatile("tcgen05.fence::after_thread_sync;" ::: "memory")
#define HX_WAIT_LD()      asm volatile("tcgen05.wait::ld.sync.aligned;" ::: "memory")
#define HX_FENCE_ASYNC()  asm volatile("fence.proxy.async.shared::cta;" ::: "memory")
#define HX_MBINIT(mb, c) \
    asm volatile("mbarrier.init.shared.b64 [%0], %1;" :: "r"((uint32_t)(mb)), "r"((uint32_t)(c)) : "memory")

#define HX_MBWAIT(mbaddr, ph) do {                                            \
    uint32_t _mb = (uint32_t)(mbaddr);                                        \
    uint32_t _pa = (uint32_t)(ph);                                            \
    uint32_t _done;                                                           \
    asm volatile("{\n\t.reg .pred p;\n\t"                                     \
        "mbarrier.try_wait.parity.acquire.cta.shared::cta.b64 p, [%1], %2;\n\t" \
        "selp.b32 %0, 1, 0, p;\n\t}" : "=r"(_done) : "r"(_mb), "r"(_pa) : "memory"); \
    if (!_done) {                                                             \
        asm volatile("{\n\t.reg .pred P1;\n\t"                                \
            "WL_%=:\n\t"                                                      \
            "mbarrier.try_wait.parity.acquire.cta.shared::cta.b64 P1, [%0], %1, 0x989680;\n\t" \
            "@P1 bra.uni WD_%=;\n\t"                                          \
            "bra.uni WL_%=;\n\t"                                              \
            "WD_%=:\n\t}" :: "r"(_mb), "r"(_pa) : "memory");                  \
    }                                                                         \
} while (0)

#define HX_CP16(dst, src) \
    asm volatile("cp.async.cg.shared.global [%0], [%1], 16;" \
                 :: "r"((uint32_t)(dst)), "l"(src) : "memory")
#define HX_CPCOMMIT() asm volatile("cp.async.commit_group;" ::: "memory")
#define HX_CPWAIT0()  asm volatile("cp.async.wait_group 0;" ::: "memory")
#define HX_CPWAIT1()  asm volatile("cp.async.wait_group 1;" ::: "memory")
#define HX_CPWAIT2()  asm volatile("cp.async.wait_group 2;" ::: "memory")

#define HX_LDTM_X32(r, addr) \
    asm volatile("tcgen05.ld.sync.aligned.32x32b.x32.b32 "                    \
        "{%0, %1, %2, %3, %4, %5, %6, %7, %8, %9, %10, %11, %12, %13, %14, %15, " \
        " %16, %17, %18, %19, %20, %21, %22, %23, %24, %25, %26, %27, %28, %29, %30, %31}, [%32];" \
        : "=r"((r)[0]),  "=r"((r)[1]),  "=r"((r)[2]),  "=r"((r)[3]),          \
          "=r"((r)[4]),  "=r"((r)[5]),  "=r"((r)[6]),  "=r"((r)[7]),          \
          "=r"((r)[8]),  "=r"((r)[9]),  "=r"((r)[10]), "=r"((r)[11]),         \
          "=r"((r)[12]), "=r"((r)[13]), "=r"((r)[14]), "=r"((r)[15]),         \
          "=r"((r)[16]), "=r"((r)[17]), "=r"((r)[18]), "=r"((r)[19]),         \
          "=r"((r)[20]), "=r"((r)[21]), "=r"((r)[22]), "=r"((r)[23]),         \
          "=r"((r)[24]), "=r"((r)[25]), "=r"((r)[26]), "=r"((r)[27]),         \
          "=r"((r)[28]), "=r"((r)[29]), "=r"((r)[30]), "=r"((r)[31])          \
        : "r"(addr))

__device__ __forceinline__ void hx_mma_f16_ss(uint32_t d, uint64_t a, uint64_t b,
                                              uint32_t idesc, uint32_t acc) {
#if HX_HAS_TCGEN05
    asm volatile("{\n\t.reg .pred p;\n\tsetp.ne.u32 p, %5, 0;\n\t"
        "tcgen05.mma.cta_group::1.kind::f16 [%0], %1, %2, %3, {%4, %4, %4, %4}, p;\n\t}"
        :: "r"(d), "l"(a), "l"(b), "r"(idesc), "r"(0u), "r"(acc) : "memory");
#endif
}

__device__ __forceinline__ uint64_t hx_desc_k(uint32_t sa) {
    return ((uint64_t)2 << 61) | ((uint64_t)1 << 46) | ((uint64_t)64 << 32) |
           ((uint64_t)1 << 16) | ((uint64_t)(sa >> 4) & 0x3FFF);
}

#define HX_IDESC_N64   0x08100010u   // f32 acc, M=128, N=64
#define HX_IDESC_N128  0x08200010u   // f32 acc, M=128, N=128

__device__ __forceinline__ uint32_t hx_offQ(int r, int c8) {
    uint32_t off = (uint32_t)((r >> 3) + ((c8 >> 3) << 4)) * 1024u +
                   (uint32_t)(r & 7) * 128u + (uint32_t)((c8 & 7) << 4);
    return off ^ ((off >> 3) & 0x70u);
}
// 256 rows x 256B tile: 2 atom columns of 32 atoms each
__device__ __forceinline__ uint32_t hx_offA(int r, int c8) {
    uint32_t off = (uint32_t)((r >> 3) + ((c8 >> 3) << 5)) * 1024u +
                   (uint32_t)(r & 7) * 128u + (uint32_t)((c8 & 7) << 4);
    return off ^ ((off >> 3) & 0x70u);
}
__device__ __forceinline__ uint32_t hx_off64w(int r, int c8) {
    uint32_t off = (uint32_t)((r >> 3) + ((c8 >> 3) << 3)) * 1024u +
                   (uint32_t)(r & 7) * 128u + (uint32_t)((c8 & 7) << 4);
    return off ^ ((off >> 3) & 0x70u);
}
__device__ __forceinline__ uint32_t hx_off128n(int r, int c8) {
    uint32_t off = (uint32_t)(r >> 3) * 1024u + (uint32_t)(r & 7) * 128u + (uint32_t)(c8 << 4);
    return off ^ ((off >> 3) & 0x70u);
}
__device__ __forceinline__ uint64_t hx_koffQ(int k) {
    return (k < 4) ? (uint64_t)(k * 2) : (uint64_t)(1024 + (k - 4) * 2);
}
// 256-row tile: atom-col 1 at 32*1024B = 2048 units
__device__ __forceinline__ uint64_t hx_koffA(int k) {
    return (k < 4) ? (uint64_t)(k * 2) : (uint64_t)(2048 + (k - 4) * 2);
}
__device__ __forceinline__ uint64_t hx_koffK(int k) {
    return (k < 4) ? (uint64_t)(k * 2) : (uint64_t)(512 + (k - 4) * 2);
}

#define MB_QKD  8
#define MB_PVD  16
#define OFF_PART 128
#define OFF_RED  1280
#define OFF_QHI  2048
#define OFF_QLO  (OFF_QHI + 32768)
#define OFF_ST0  (OFF_QLO + 32768)     // 67584 (1024-aligned)
#define STB      65536
#define ST_A(s)   (OFF_ST0 + (s) * STB)       // pass A: 256 keys x 256B
#define ST_KHI(s) (OFF_ST0 + (s) * STB)
#define ST_KLO(s) (ST_KHI(s) + 16384)
#define ST_KT(s)  (ST_KHI(s) + 32768)
#define ST_VT(s)  (ST_KHI(s) + 49152)
#define OFF_P(s)  (OFF_ST0 + 2 * STB + 16384 * (s))
#define SMEM_TOTAL (OFF_ST0 + 2 * STB + 32768)        // 231424 <= 232448

#define TMA_S(s) (256 * (s))   // pass A: f32 S, 2 x N=128 per stage
#define TMB_S(s) (64 * (s))
#define TM_OK    256
#define TM_OV    384

__global__ void prep_hilo(const float* __restrict__ q, const float* __restrict__ k) {
    int i = blockIdx.x * blockDim.x + threadIdx.x;
    if (i < NKEYS * D) {
        float x = k[i];
        __half h = __float2half_rn(x);
        g_khi[i] = h;
        g_klo[i] = __float2half_rn(x - __half2float(h));
    }
    if (i < NQ * D) {
        float x = q[i];
        __half h = __float2half_rn(x);
        g_qhi[i] = h;
        g_qlo[i] = __float2half_rn(x - __half2float(h));
    }
}

__global__ void prep_transpose(const float* __restrict__ k, const float* __restrict__ v) {
    __shared__ __half sm[32][33];
    const float* src = blockIdx.z ? v : k;
    __half* dst = blockIdx.z ? g_vthi : g_kthi;
    int n0 = blockIdx.x * 32;
    int d0 = blockIdx.y * 32;
    #pragma unroll
    for (int yy = threadIdx.y; yy < 32; yy += 8)
        sm[yy][threadIdx.x] = __float2half_rn(src[(size_t)(n0 + yy) * D + d0 + threadIdx.x]);
    __syncthreads();
    #pragma unroll
    for (int yy = threadIdx.y; yy < 32; yy += 8)
        dst[(size_t)(d0 + yy) * NKEYS + n0 + threadIdx.x] = sm[threadIdx.x][yy];
}

__global__ __launch_bounds__(NTHREADS, 1) void flash_main() {
#if HX_HAS_TCGEN05
    extern __shared__ char smem[];
    uint32_t sb = hx_smem_u32(smem);
    int tid = threadIdx.x;
    int wid = tid >> 5;
    int lane = tid & 31;
    int colh = wid >> 2;
    int row  = 32 * (wid & 3) + lane;

    int split = blockIdx.x & (NSPLIT - 1);
    int q0 = (blockIdx.x >> 2) * 128;
    int n0 = split * KEYS_PER_SPLIT;

    if (wid == 0) HX_TCALLOC(sb, 512);
    if (tid == 0) { HX_MBINIT(sb + MB_QKD, 1); HX_MBINIT(sb + MB_PVD, 1); }
    __syncthreads();
    uint32_t tmem;
    asm volatile("ld.shared.b32 %0, [%1];" : "=r"(tmem) : "r"(sb));

    #pragma unroll
    for (int i = 0; i < 8; ++i) {
        int idx = tid + i * 256;
        int r = idx >> 4, c8 = idx & 15;
        size_t go = (size_t)(q0 + r) * D + (size_t)c8 * 8;
        *(uint4*)(smem + OFF_QHI + hx_offQ(r, c8)) = *(const uint4*)(g_qhi + go);
        *(uint4*)(smem + OFF_QLO + hx_offQ(r, c8)) = *(const uint4*)(g_qlo + go);
    }
    HX_FENCE_ASYNC();
    __syncthreads();

    uint64_t dqh = hx_desc_k(sb + OFF_QHI);
    uint64_t dql = hx_desc_k(sb + OFF_QLO);
    uint64_t dka[2], dkh[2], dkl[2], dkt[2], dvt[2], dpp[2];
    #pragma unroll
    for (int s = 0; s < 2; ++s) {
        dka[s] = hx_desc_k(sb + ST_A(s));
        dkh[s] = hx_desc_k(sb + ST_KHI(s));
        dkl[s] = hx_desc_k(sb + ST_KLO(s));
        dkt[s] = hx_desc_k(sb + ST_KT(s));
        dvt[s] = hx_desc_k(sb + ST_VT(s));
        dpp[s] = hx_desc_k(sb + OFF_P(s));
    }
    uint32_t lead = (wid == 0) ? hx_elect() : 0;

    int phq = 0, php = 0;
    float m = -1e30f, lsum = 0.0f;

    // ====== PASS A: row max (BNA=256 = 2 x N=128 f32 MMAs per tile) =========
    #define LOADA(t, s_) do {                                                  \
        const __half* _src = g_khi + (size_t)(n0 + (t) * BNA) * D;             \
        _Pragma("unroll")                                                      \
        for (int _j = 0; _j < 16; ++_j) {                                      \
            int _idx = tid + _j * 256;                                         \
            int _r = _idx >> 4, _c8 = _idx & 15;                               \
            HX_CP16(sb + ST_A(s_) + hx_offA(_r, _c8),                          \
                    _src + (size_t)_r * D + (size_t)_c8 * 8);                  \
        }                                                                      \
    } while (0)

    #define QKA(s_) do {                                                       \
        _Pragma("unroll")                                                      \
        for (int kk = 0; kk < 8; ++kk)                                         \
            hx_mma_f16_ss(tmem + TMA_S(s_), dqh + hx_koffQ(kk),                \
                          dka[s_] + hx_koffA(kk), HX_IDESC_N128, kk > 0);      \
        _Pragma("unroll")                                                      \
        for (int kk = 0; kk < 8; ++kk)                                         \
            hx_mma_f16_ss(tmem + TMA_S(s_) + 128, dqh + hx_koffQ(kk),          \
                          dka[s_] + 1024 + hx_koffA(kk), HX_IDESC_N128, kk > 0); \
        HX_COMMIT(sb + MB_QKD);                                                \
    } while (0)

    LOADA(0, 0); HX_CPCOMMIT();
    LOADA(1, 1); HX_CPCOMMIT();
    HX_CPWAIT1(); HX_FENCE_ASYNC(); __syncthreads();
    if (lead) QKA(0);

    for (int t = 0; t < NTA; ++t) {
        int s = t & 1;
        HX_MBWAIT(sb + MB_QKD, phq); phq ^= 1;
        if (t + 2 < NTA) LOADA(t + 2, s);
        HX_CPCOMMIT();
        HX_CPWAIT1(); HX_FENCE_ASYNC(); __syncthreads();
        if (t + 1 < NTA && lead) QKA(s ^ 1);
        HX_FENCE_AFTER();
        uint32_t r0[32], r1[32];
        HX_LDTM_X32(r0, tmem + TMA_S(s) + 64 * colh);
        HX_LDTM_X32(r1, tmem + TMA_S(s) + 64 * colh + 32);
        HX_WAIT_LD();
        #pragma unroll
        for (int j = 0; j < 32; ++j) {
            m = fmaxf(m, __uint_as_float(r0[j]));
            m = fmaxf(m, __uint_as_float(r1[j]));
        }
        HX_LDTM_X32(r0, tmem + TMA_S(s) + 128 + 64 * colh);
        HX_LDTM_X32(r1, tmem + TMA_S(s) + 128 + 64 * colh + 32);
        HX_WAIT_LD();
        HX_FENCE_BEFORE();
        #pragma unroll
        for (int j = 0; j < 32; ++j) {
            m = fmaxf(m, __uint_as_float(r0[j]));
            m = fmaxf(m, __uint_as_float(r1[j]));
        }
    }
    HX_CPWAIT0();
    __syncthreads();

    {
        float* part = (float*)(smem + OFF_PART);
        float* red  = (float*)(smem + OFF_RED);
        part[tid] = m;
        __syncthreads();
        if (tid < 128) red[tid] = fmaxf(part[tid], part[tid + 128]);
        __syncthreads();
        m = red[row];
        __syncthreads();
    }

    // ======================= PASS B: softmax + PV (BNB=64) ==================
    #define LOADB_KHILO(t, s_) do {                                            \
        size_t _nb = (size_t)(n0 + (t) * BNB);                                 \
        const __half* _skh = g_khi + _nb * D;                                  \
        const __half* _skl = g_klo + _nb * D;                                  \
        _Pragma("unroll")                                                      \
        for (int _j = 0; _j < 4; ++_j) {                                       \
            int _idx = tid + _j * 256;                                         \
            int _r = _idx >> 4, _c8 = _idx & 15;                               \
            uint32_t _so = hx_off64w(_r, _c8);                                 \
            size_t _go = (size_t)_r * D + (size_t)_c8 * 8;                     \
            HX_CP16(sb + ST_KHI(s_) + _so, _skh + _go);                        \
            HX_CP16(sb + ST_KLO(s_) + _so, _skl + _go);                        \
        }                                                                      \
    } while (0)
    #define LOADB_KTVT(t, s_) do {                                             \
        size_t _nb = (size_t)(n0 + (t) * BNB);                                 \
        const __half* _skt = g_kthi + _nb;                                     \
        const __half* _svt = g_vthi + _nb;                                     \
        _Pragma("unroll")                                                      \
        for (int _j = 0; _j < 4; ++_j) {                                       \
            int _idx = tid + _j * 256;                                         \
            int _r = _idx >> 3, _c8 = _idx & 7;                                \
            uint32_t _so = hx_off128n(_r, _c8);                                \
            size_t _go = (size_t)_r * NKEYS + (size_t)_c8 * 8;                 \
            HX_CP16(sb + ST_KT(s_) + _so, _skt + _go);                         \
            HX_CP16(sb + ST_VT(s_) + _so, _svt + _go);                         \
        }                                                                      \
    } while (0)

    LOADB_KHILO(0, 0); LOADB_KTVT(0, 0); HX_CPCOMMIT();
    LOADB_KHILO(1, 1); HX_CPCOMMIT();
    HX_CPWAIT1(); HX_FENCE_ASYNC(); __syncthreads();
    if (lead) {
        #pragma unroll
        for (int kk = 0; kk < 8; ++kk)
            hx_mma_f16_ss(tmem + TMB_S(0), dqh + hx_koffQ(kk),
                          dkh[0] + hx_koffK(kk), HX_IDESC_N64, kk > 0);
        #pragma unroll
        for (int kk = 0; kk < 8; ++kk)
            hx_mma_f16_ss(tmem + TMB_S(0), dqh + hx_koffQ(kk),
                          dkl[0] + hx_koffK(kk), HX_IDESC_N64, 1u);
        #pragma unroll
        for (int kk = 0; kk < 8; ++kk)
            hx_mma_f16_ss(tmem + TMB_S(0), dql + hx_koffQ(kk),
                          dkh[0] + hx_koffK(kk), HX_IDESC_N64, 1u);
        HX_COMMIT(sb + MB_QKD);
    }

    for (int t = 0; t < NTB; ++t) {
        int s = t & 1;
        HX_MBWAIT(sb + MB_QKD, phq); phq ^= 1;
        if (t + 2 < NTB) LOADB_KHILO(t + 2, s);
        HX_CPCOMMIT();
        if (t >= 1) { HX_MBWAIT(sb + MB_PVD, php); php ^= 1; }
        if (t + 1 < NTB) LOADB_KTVT(t + 1, s ^ 1);
        HX_CPCOMMIT();
        HX_CPWAIT2(); HX_FENCE_ASYNC(); __syncthreads();
        if (t + 1 < NTB && lead) {
            int s1 = s ^ 1;
            #pragma unroll
            for (int kk = 0; kk < 8; ++kk)
                hx_mma_f16_ss(tmem + TMB_S(s1), dqh + hx_koffQ(kk),
                              dkh[s1] + hx_koffK(kk), HX_IDESC_N64, kk > 0);
            #pragma unroll
            for (int kk = 0; kk < 8; ++kk)
                hx_mma_f16_ss(tmem + TMB_S(s1), dqh + hx_koffQ(kk),
                              dkl[s1] + hx_koffK(kk), HX_IDESC_N64, 1u);
            #pragma unroll
            for (int kk = 0; kk < 8; ++kk)
                hx_mma_f16_ss(tmem + TMB_S(s1), dql + hx_koffQ(kk),
                              dkh[s1] + hx_koffK(kk), HX_IDESC_N64, 1u);
            HX_COMMIT(sb + MB_QKD);
        }
        HX_FENCE_AFTER();
        uint32_t r[32];
        HX_LDTM_X32(r, tmem + TMB_S(s) + 32 * colh);
        HX_WAIT_LD();
        HX_FENCE_BEFORE();
        #pragma unroll
        for (int u = 0; u < 4; ++u) {
            uint32_t h2[4];
            #pragma unroll
            for (int j = 0; j < 4; ++j) {
                float p0 = __expf(__uint_as_float(r[8 * u + 2 * j])     - m);
                float p1 = __expf(__uint_as_float(r[8 * u + 2 * j + 1]) - m);
                lsum += p0 + p1;
                __half2 hh = __floats2half2_rn(p0, p1);
                h2[j] = *(uint32_t*)&hh;
            }
            *(uint4*)(smem + OFF_P(s) + hx_off128n(row, 4 * colh + u)) =
                make_uint4(h2[0], h2[1], h2[2], h2[3]);
        }
        HX_FENCE_ASYNC();
        __syncthreads();
        if (lead) {
            #pragma unroll
            for (int kk = 0; kk < 4; ++kk) {
                uint32_t acc = (t > 0 || kk > 0) ? 1u : 0u;
                hx_mma_f16_ss(tmem + TM_OK, dpp[s] + 2 * kk, dkt[s] + 2 * kk,
                              HX_IDESC_N128, acc);
                hx_mma_f16_ss(tmem + TM_OV, dpp[s] + 2 * kk, dvt[s] + 2 * kk,
                              HX_IDESC_N128, acc);
            }
            HX_COMMIT(sb + MB_PVD);
        }
    }
    HX_MBWAIT(sb + MB_PVD, php); php ^= 1;
    HX_CPWAIT0();
    __syncthreads();

    // ======================= epilogue ========================================
    {
        float* part = (float*)(smem + OFF_PART);
        float* red  = (float*)(smem + OFF_RED);
        part[tid] = lsum;
        __syncthreads();
        if (tid < 128) {
            red[tid] = part[tid] + part[tid + 128];
            g_m[split * NQ + q0 + tid] = m;
            g_l[split * NQ + q0 + tid] = red[tid];
        }
    }
    HX_FENCE_AFTER();
    size_t base = ((size_t)split * NQ + q0 + row) * D + 64 * colh;
    #pragma unroll
    for (int c = 0; c < 2; ++c) {
        uint32_t rk[32];
        HX_LDTM_X32(rk, tmem + TM_OK + 64 * colh + 32 * c);
        HX_WAIT_LD();
        #pragma unroll
        for (int j = 0; j < 32; ++j)
            g_ok[base + 32 * c + j] = __uint_as_float(rk[j]);
    }
    #pragma unroll
    for (int c = 0; c < 2; ++c) {
        uint32_t rv[32];
        HX_LDTM_X32(rv, tmem + TM_OV + 64 * colh + 32 * c);
        HX_WAIT_LD();
        #pragma unroll
        for (int j = 0; j < 32; ++j)
            g_ov[base + 32 * c + j] = __uint_as_float(rv[j]);
    }
    HX_FENCE_BEFORE();
    __syncthreads();
    if (wid == 0) HX_TCDEALLOC(tmem, 512);
#endif
}

__global__ void reduce_kernel(float* __restrict__ out) {
    int q = blockIdx.x;
    int d = threadIdx.x;
    float m0 = g_m[q], m1 = g_m[NQ + q], m2 = g_m[2 * NQ + q], m3 = g_m[3 * NQ + q];
    float ms = fmaxf(fmaxf(m0, m1), fmaxf(m2, m3));
    float w0 = __expf(m0 - ms), w1 = __expf(m1 - ms);
    float w2 = __expf(m2 - ms), w3 = __expf(m3 - ms);
    float inv = 1.0f / (g_l[q] * w0 + g_l[NQ + q] * w1 +
                        g_l[2 * NQ + q] * w2 + g_l[3 * NQ + q] * w3);
    size_t i0 = (size_t)q * D + d;
    size_t i1 = ((size_t)NQ + q) * D + d;
    size_t i2 = ((size_t)2 * NQ + q) * D + d;
    size_t i3 = ((size_t)3 * NQ + q) * D + d;
    float ok = g_ok[i0] * w0 + g_ok[i1] * w1 + g_ok[i2] * w2 + g_ok[i3] * w3;
    float ov = g_ov[i0] * w0 + g_ov[i1] * w1 + g_ov[i2] * w2 + g_ov[i3] * w3;
    out[(size_t)q * D + d] = ok * inv;
    out[(size_t)NQ * D + (size_t)q * D + d] = ov * inv;
}

extern "C" void kernel_launch(void* const* d_in, const int* in_sizes, int n_in,
                              void* d_out, int out_size) {
    const float* q = (const float*)d_in[0];
    const float* k = (const float*)d_in[1];
    const float* v = (const float*)d_in[2];
    float* out = (float*)d_out;
    (void)in_sizes; (void)n_in; (void)out_size;

    cudaFuncSetAttribute(flash_main, cudaFuncAttributeMaxDynamicSharedMemorySize, SMEM_TOTAL);
    prep_hilo<<<(NKEYS * D) / 256, 256>>>(q, k);
    dim3 gt(NKEYS / 32, D / 32, 2), bt(32, 8);
    prep_transpose<<<gt, bt>>>(k, v);
    flash_main<<<NCTA, NTHREADS, SMEM_TOTAL>>>();
    reduce_kernel<<<NQ, 128>>>(out);
}